// round 1
// baseline (speedup 1.0000x reference)
#include <cuda_runtime.h>
#include <math.h>

#define NCRYST 64
#define ATOMS  32
#define NATOM  2048
#define NBR    20
#define NEDGE  40960
#define CCH    128
#define HID    256
#define NBIN   128
#define NLAYER 8
#define KH     19

// ---------------- scratch (device globals; no allocation allowed) ----------------
__device__ float g_pos [NATOM * 3];
__device__ float g_dirn[NEDGE * 3];
__device__ float g_Y   [NEDGE * KH];
__device__ float g_rbf [NEDGE * NBIN];
__device__ float g_x   [NATOM * KH * CCH];
__device__ float g_s   [NEDGE * CCH];
__device__ float g_m   [NEDGE * CCH];
__device__ float g_zc  [NCRYST * CCH];
__device__ float g_hw  [NATOM];

// ---------------- k_prep: lattice, positions, z @ zproj ----------------
__global__ void k_prep(const float* __restrict__ z, const float* __restrict__ frac,
                       const float* __restrict__ lengths, const float* __restrict__ angles,
                       const float* __restrict__ zproj) {
    int cb = blockIdx.x, tid = threadIdx.x;
    __shared__ float lat[9];
    __shared__ float zs[256];
    if (tid == 0) {
        float a = lengths[cb*3+0], b = lengths[cb*3+1], c = lengths[cb*3+2];
        const float D2R = 0.017453292519943295f;
        float r0 = angles[cb*3+0]*D2R, r1 = angles[cb*3+1]*D2R, r2 = angles[cb*3+2]*D2R;
        float ca = cosf(r0), cbta = cosf(r1), cg = cosf(r2), sg = sinf(r2);
        float v3y = (ca - cbta*cg)/sg;
        float t = 1.0f - cbta*cbta - v3y*v3y;
        if (t < 1e-8f) t = 1e-8f;
        float v3z = sqrtf(t);
        lat[0]=a;        lat[1]=0.f;     lat[2]=0.f;
        lat[3]=b*cg;     lat[4]=b*sg;    lat[5]=0.f;
        lat[6]=c*cbta;   lat[7]=c*v3y;   lat[8]=c*v3z;
    }
    for (int i = tid; i < 256; i += blockDim.x) zs[i] = z[cb*256 + i];
    __syncthreads();
    if (tid < 96) {
        int a = tid/3, j = tid%3;
        int n = cb*ATOMS + a;
        g_pos[n*3+j] = frac[n*3+0]*lat[0+j] + frac[n*3+1]*lat[3+j] + frac[n*3+2]*lat[6+j];
    }
    // z @ zproj  (128 outputs per crystal)
    float acc = 0.f;
    for (int i = 0; i < 256; i++) acc += zs[i]*zproj[i*CCH + tid];
    g_zc[cb*CCH + tid] = acc;
}

// ---------------- k_xinit: x[:,0,:] = emb[type] + zc[batch]; rest = 0 ----------------
__global__ void k_xinit(const int* __restrict__ types, const int* __restrict__ batch,
                        const float* __restrict__ emb) {
    int n = blockIdx.x, c = threadIdx.x;
    int t = types[n];
    g_x[(n*KH + 0)*CCH + c] = emb[t*CCH + c] + g_zc[batch[n]*CCH + c];
    #pragma unroll
    for (int k = 1; k < KH; k++) g_x[(n*KH + k)*CCH + c] = 0.f;
}

// ---------------- k_edge: dirn, Y (sph harm), rbf ----------------
__global__ void k_edge(const int* __restrict__ ei) {
    int tid = threadIdx.x;
    int e0 = blockIdx.x * 32;
    __shared__ float ds[32];
    if (tid < 32) {
        int e = e0 + tid;
        int s = ei[e], d = ei[NEDGE + e];
        float vx = g_pos[s*3+0]-g_pos[d*3+0];
        float vy = g_pos[s*3+1]-g_pos[d*3+1];
        float vz = g_pos[s*3+2]-g_pos[d*3+2];
        float dist = sqrtf(vx*vx + vy*vy + vz*vz) + 1e-8f;
        ds[tid] = dist;
        float dx = vx/dist, dy = vy/dist, dz = vz/dist;
        g_dirn[e*3+0]=dx; g_dirn[e*3+1]=dy; g_dirn[e*3+2]=dz;
        float ct = dz;
        float rho = sqrtf(dx*dx + dy*dy) + 1e-12f;
        float cph = dx/rho, sph = dy/rho;
        float P0[7]; P0[0]=1.f; P0[1]=ct;
        #pragma unroll
        for (int l=2;l<=6;l++) P0[l] = ((2*l-1)*ct*P0[l-1] - (l-1)*P0[l-2]) / l;
        float P1[7]; P1[0]=0.f; P1[1]=-rho; P1[2]=-3.f*ct*rho;
        #pragma unroll
        for (int l=3;l<=6;l++) P1[l] = ((2*l-1)*ct*P1[l-1] - l*P1[l-2]) / (l-1);
        float* Yp = &g_Y[e*KH];
        const float FPI = 12.566370614359172f;
        Yp[0] = 0.28209479177387814f;
        int idx = 1;
        #pragma unroll
        for (int l=1;l<=6;l++) {
            float K0 = sqrtf((2*l+1)/FPI);
            float K1 = sqrtf(2.f*(2*l+1)/(FPI*l*(l+1)));
            Yp[idx++] = K1*P1[l]*sph;
            Yp[idx++] = K0*P0[l];
            Yp[idx++] = K1*P1[l]*cph;
        }
    }
    __syncthreads();
    const float step = 8.0f/127.0f;
    const float inv  = 127.0f/8.0f;
    for (int el = 0; el < 32; el++) {
        float d = ds[el];
        float t = (d - step*(float)tid)*inv;
        g_rbf[(e0+el)*NBIN + tid] = expf(-0.5f*t*t);
    }
}

// ---------------- k_s: s[e,c] = sum_k Y[e,k] * x[src[e],k,c]  (per-crystal, per c-half) ----------------
__global__ __launch_bounds__(256) void k_s(const int* __restrict__ ei) {
    int chalf = blockIdx.x;      // 0..1
    int cb    = blockIdx.y;      // crystal
    int tid   = threadIdx.x;
    extern __shared__ float sm[];
    float* xs  = sm;                       // 32*19*64
    float* Ys  = sm + ATOMS*KH*64;         // 640*19
    int*   srcs = (int*)(Ys + 640*KH);     // 640
    int abase = cb*ATOMS;
    int c0 = chalf*64;
    for (int i = tid; i < ATOMS*KH*64; i += 256) {
        int a = i/(KH*64); int r = i - a*(KH*64); int k = r >> 6; int c = r & 63;
        xs[i] = g_x[((abase+a)*KH + k)*CCH + c0 + c];
    }
    int ebase = cb*640;
    for (int i = tid; i < 640*KH; i += 256) Ys[i] = g_Y[ebase*KH + i];
    for (int i = tid; i < 640; i += 256) srcs[i] = ei[ebase + i] - abase;
    __syncthreads();
    int cl = tid & 63, er = tid >> 6;
    for (int j = 0; j < 160; j++) {
        int e = j*4 + er;
        int sl = srcs[e];
        const float* xr = &xs[sl*(KH*64) + cl];
        const float* yr = &Ys[e*KH];
        float acc = 0.f;
        #pragma unroll
        for (int k = 0; k < KH; k++) acc += yr[k]*xr[k*64];
        g_s[(ebase+e)*CCH + c0 + cl] = acc;
    }
}

// ---------------- k_mlp: h = silu([s|rbf] @ [W1;Wd]); m = h @ W2 ----------------
__global__ __launch_bounds__(256) void k_mlp(const float* __restrict__ W1,
                                             const float* __restrict__ Wd,
                                             const float* __restrict__ W2,
                                             int layer) {
    int tid = threadIdx.x;
    int e0  = blockIdx.x * 64;
    extern __shared__ float sm[];
    float* aT = sm;                  // 64 x 257 (s | rbf)
    float* hT = sm + 64*257;         // 64 x 257
    float* wS = sm + 2*64*257;       // 16*256 floats

    for (int i = tid; i < 64*128; i += 256) {
        int r = i >> 7, c = i & 127;
        aT[r*257 + c]       = g_s  [(e0 + r)*CCH  + c];
        aT[r*257 + 128 + c] = g_rbf[(e0 + r)*NBIN + c];
    }
    __syncthreads();

    const int tx = tid & 31, ty = tid >> 5;
    const int h0 = tx*8, r0 = ty*8;
    float acc[8][8];
    #pragma unroll
    for (int i = 0; i < 8; i++)
        #pragma unroll
        for (int j = 0; j < 8; j++) acc[i][j] = 0.f;

    const float* W1l = W1 + layer*CCH*HID;
    const float* Wdl = Wd + layer*NBIN*HID;

    for (int kk = 0; kk < 256; kk += 16) {
        for (int i = tid; i < 16*256; i += 256) {
            int kr = i >> 8, h = i & 255;
            int k = kk + kr;
            wS[i] = (k < 128) ? W1l[k*HID + h] : Wdl[(k-128)*HID + h];
        }
        __syncthreads();
        #pragma unroll
        for (int k = 0; k < 16; k++) {
            float a[8];
            #pragma unroll
            for (int i = 0; i < 8; i++) a[i] = aT[(r0+i)*257 + kk + k];
            float4 b0 = *(const float4*)&wS[k*256 + h0];
            float4 b1 = *(const float4*)&wS[k*256 + h0 + 4];
            float b[8] = {b0.x,b0.y,b0.z,b0.w,b1.x,b1.y,b1.z,b1.w};
            #pragma unroll
            for (int i = 0; i < 8; i++)
                #pragma unroll
                for (int j = 0; j < 8; j++) acc[i][j] = fmaf(a[i], b[j], acc[i][j]);
        }
        __syncthreads();
    }

    #pragma unroll
    for (int i = 0; i < 8; i++)
        #pragma unroll
        for (int j = 0; j < 8; j++) {
            float v = acc[i][j];
            hT[(r0+i)*257 + h0 + j] = v / (1.f + expf(-v));   // silu
        }
    __syncthreads();

    const int c0 = tx*4;
    float acc2[8][4];
    #pragma unroll
    for (int i = 0; i < 8; i++)
        #pragma unroll
        for (int j = 0; j < 4; j++) acc2[i][j] = 0.f;

    const float* W2l = W2 + layer*HID*CCH;
    for (int kk = 0; kk < 256; kk += 16) {
        for (int i = tid; i < 16*128; i += 256) {
            int kr = i >> 7, c = i & 127;
            wS[i] = W2l[(kk + kr)*CCH + c];
        }
        __syncthreads();
        #pragma unroll
        for (int k = 0; k < 16; k++) {
            float a[8];
            #pragma unroll
            for (int i = 0; i < 8; i++) a[i] = hT[(r0+i)*257 + kk + k];
            float4 bv = *(const float4*)&wS[k*128 + c0];
            #pragma unroll
            for (int i = 0; i < 8; i++) {
                acc2[i][0] = fmaf(a[i], bv.x, acc2[i][0]);
                acc2[i][1] = fmaf(a[i], bv.y, acc2[i][1]);
                acc2[i][2] = fmaf(a[i], bv.z, acc2[i][2]);
                acc2[i][3] = fmaf(a[i], bv.w, acc2[i][3]);
            }
        }
        __syncthreads();
    }
    #pragma unroll
    for (int i = 0; i < 8; i++) {
        float4 o = make_float4(acc2[i][0], acc2[i][1], acc2[i][2], acc2[i][3]);
        *(float4*)&g_m[(e0 + r0 + i)*CCH + c0] = o;
    }
}

// ---------------- k_agg: x[n,k,c] += (1/NBR) * sum_e Y[e,k]*m[e,c]  (dst-contiguous) ----------------
__global__ void k_agg() {
    int n = blockIdx.x, tid = threadIdx.x;
    __shared__ float mS[NBR*CCH];
    __shared__ float yS[NBR*KH];
    int eb = n*NBR;
    for (int i = tid; i < NBR*CCH; i += 128) mS[i] = g_m[eb*CCH + i];
    for (int i = tid; i < NBR*KH;  i += 128) yS[i] = g_Y[eb*KH + i];
    __syncthreads();
    int c = tid;
    float acc[KH];
    #pragma unroll
    for (int k = 0; k < KH; k++) acc[k] = 0.f;
    #pragma unroll
    for (int e = 0; e < NBR; e++) {
        float mv = mS[e*CCH + c];
        #pragma unroll
        for (int k = 0; k < KH; k++) acc[k] = fmaf(yS[e*KH + k], mv, acc[k]);
    }
    #pragma unroll
    for (int k = 0; k < KH; k++) g_x[(n*KH + k)*CCH + c] += acc[k]*0.05f;
}

// ---------------- k_hw: hw[n] = h_node[n] . wf ----------------
__global__ void k_hw(const float* __restrict__ wf) {
    int n = blockIdx.x, lane = threadIdx.x;
    float v = 0.f;
    for (int c = lane; c < CCH; c += 32) v += g_x[n*(KH*CCH) + c]*wf[c];
    #pragma unroll
    for (int off = 16; off; off >>= 1) v += __shfl_xor_sync(0xffffffffu, v, off);
    if (lane == 0) g_hw[n] = v;
}

// ---------------- k_out: logits + coord_diff ----------------
__global__ void k_out(const float* __restrict__ Wa, const float* __restrict__ ba,
                      const int* __restrict__ ei, float* __restrict__ out) {
    int n = blockIdx.x, tid = threadIdx.x;
    __shared__ float hs[CCH];
    hs[tid] = g_x[n*(KH*CCH) + tid];
    __syncthreads();
    if (tid < 100) {
        float acc = ba[tid];
        for (int c = 0; c < CCH; c++) acc = fmaf(hs[c], Wa[c*100 + tid], acc);
        out[NATOM*3 + n*100 + tid] = acc;
    } else if (tid < 103) {
        int j = tid - 100;
        float hwn = g_hw[n];
        float acc = 0.f;
        for (int e = 0; e < NBR; e++) {
            int ge = n*NBR + e;
            acc = fmaf(g_hw[ei[ge]] - hwn, g_dirn[ge*3 + j], acc);
        }
        out[n*3 + j] = acc;
    }
}

// ---------------- launch ----------------
static const int SMEM_A = (ATOMS*KH*64 + 640*KH + 640) * 4;   // 206848 B
static const int SMEM_B = (2*64*257 + 16*256) * 4;            // 147968 B

extern "C" void kernel_launch(void* const* d_in, const int* in_sizes, int n_in,
                              void* d_out, int out_size) {
    const float* z       = (const float*)d_in[0];
    const float* frac    = (const float*)d_in[1];
    const int*   types   = (const int*)  d_in[2];
    const float* lengths = (const float*)d_in[4];
    const float* angles  = (const float*)d_in[5];
    const int*   batch   = (const int*)  d_in[6];
    const int*   ei      = (const int*)  d_in[7];
    const float* emb     = (const float*)d_in[8];
    const float* zproj   = (const float*)d_in[9];
    const float* Wd      = (const float*)d_in[10];
    const float* W1      = (const float*)d_in[11];
    const float* W2      = (const float*)d_in[12];
    const float* Wa      = (const float*)d_in[13];
    const float* ba      = (const float*)d_in[14];
    const float* wf      = (const float*)d_in[15];
    float* out = (float*)d_out;

    cudaFuncSetAttribute(k_s,   cudaFuncAttributeMaxDynamicSharedMemorySize, SMEM_A);
    cudaFuncSetAttribute(k_mlp, cudaFuncAttributeMaxDynamicSharedMemorySize, SMEM_B);

    k_prep <<<NCRYST, 128>>>(z, frac, lengths, angles, zproj);
    k_xinit<<<NATOM, 128>>>(types, batch, emb);
    k_edge <<<NEDGE/32, 128>>>(ei);
    for (int l = 0; l < NLAYER; l++) {
        k_s  <<<dim3(2, NCRYST), 256, SMEM_A>>>(ei);
        k_mlp<<<NEDGE/64, 256, SMEM_B>>>(W1, Wd, W2, l);
        k_agg<<<NATOM, 128>>>();
    }
    k_hw <<<NATOM, 32>>>(wf);
    k_out<<<NATOM, 128>>>(Wa, ba, ei, out);
}

// round 2
// speedup vs baseline: 1.3232x; 1.3232x over previous
#include <cuda_runtime.h>
#include <math.h>

#define NCRYST 64
#define ATOMS  32
#define NATOM  2048
#define NBR    20
#define NEDGE  40960
#define CCH    128
#define HID    256
#define NBIN   128
#define NLAYER 8
#define KH     19

typedef unsigned long long u64;

// ---------------- packed f32x2 helpers (Blackwell FFMA2) ----------------
__device__ __forceinline__ u64 pack_dup(float v) {
    u64 r;
    asm("mov.b64 %0, {%1, %1};" : "=l"(r) : "f"(v));
    return r;
}
__device__ __forceinline__ void ffma2(u64& d, u64 a, u64 b) {
    asm("fma.rn.f32x2 %0, %1, %2, %0;" : "+l"(d) : "l"(a), "l"(b));
}
__device__ __forceinline__ void unpack2(u64 v, float& lo, float& hi) {
    asm("mov.b64 {%0, %1}, %2;" : "=f"(lo), "=f"(hi) : "l"(v));
}
__device__ __forceinline__ u64 pack2(float lo, float hi) {
    u64 r;
    asm("mov.b64 %0, {%1, %2};" : "=l"(r) : "f"(lo), "f"(hi));
    return r;
}

// ---------------- scratch ----------------
__device__ float g_pos [NATOM * 3];
__device__ float g_dirn[NEDGE * 3];
__device__ float g_Y   [NEDGE * KH];
__device__ float g_rbf [NEDGE * NBIN];
__device__ float g_x   [NATOM * KH * CCH];
__device__ float g_s   [NEDGE * CCH];
__device__ float g_m   [NEDGE * CCH];
__device__ float g_zc  [NCRYST * CCH];
__device__ float g_hw  [NATOM];

// ---------------- k_prep ----------------
__global__ void k_prep(const float* __restrict__ z, const float* __restrict__ frac,
                       const float* __restrict__ lengths, const float* __restrict__ angles,
                       const float* __restrict__ zproj) {
    int cb = blockIdx.x, tid = threadIdx.x;
    __shared__ float lat[9];
    __shared__ float zs[256];
    if (tid == 0) {
        float a = lengths[cb*3+0], b = lengths[cb*3+1], c = lengths[cb*3+2];
        const float D2R = 0.017453292519943295f;
        float r0 = angles[cb*3+0]*D2R, r1 = angles[cb*3+1]*D2R, r2 = angles[cb*3+2]*D2R;
        float ca = cosf(r0), cbta = cosf(r1), cg = cosf(r2), sg = sinf(r2);
        float v3y = (ca - cbta*cg)/sg;
        float t = 1.0f - cbta*cbta - v3y*v3y;
        if (t < 1e-8f) t = 1e-8f;
        float v3z = sqrtf(t);
        lat[0]=a;        lat[1]=0.f;     lat[2]=0.f;
        lat[3]=b*cg;     lat[4]=b*sg;    lat[5]=0.f;
        lat[6]=c*cbta;   lat[7]=c*v3y;   lat[8]=c*v3z;
    }
    for (int i = tid; i < 256; i += blockDim.x) zs[i] = z[cb*256 + i];
    __syncthreads();
    if (tid < 96) {
        int a = tid/3, j = tid%3;
        int n = cb*ATOMS + a;
        g_pos[n*3+j] = frac[n*3+0]*lat[0+j] + frac[n*3+1]*lat[3+j] + frac[n*3+2]*lat[6+j];
    }
    float acc = 0.f;
    for (int i = 0; i < 256; i++) acc += zs[i]*zproj[i*CCH + tid];
    g_zc[cb*CCH + tid] = acc;
}

// ---------------- k_xinit ----------------
__global__ void k_xinit(const int* __restrict__ types, const int* __restrict__ batch,
                        const float* __restrict__ emb) {
    int n = blockIdx.x, c = threadIdx.x;
    int t = types[n];
    g_x[(n*KH + 0)*CCH + c] = emb[t*CCH + c] + g_zc[batch[n]*CCH + c];
    #pragma unroll
    for (int k = 1; k < KH; k++) g_x[(n*KH + k)*CCH + c] = 0.f;
}

// ---------------- k_edge ----------------
__global__ void k_edge(const int* __restrict__ ei) {
    int tid = threadIdx.x;
    int e0 = blockIdx.x * 32;
    __shared__ float ds[32];
    if (tid < 32) {
        int e = e0 + tid;
        int s = ei[e], d = ei[NEDGE + e];
        float vx = g_pos[s*3+0]-g_pos[d*3+0];
        float vy = g_pos[s*3+1]-g_pos[d*3+1];
        float vz = g_pos[s*3+2]-g_pos[d*3+2];
        float dist = sqrtf(vx*vx + vy*vy + vz*vz) + 1e-8f;
        ds[tid] = dist;
        float dx = vx/dist, dy = vy/dist, dz = vz/dist;
        g_dirn[e*3+0]=dx; g_dirn[e*3+1]=dy; g_dirn[e*3+2]=dz;
        float ct = dz;
        float rho = sqrtf(dx*dx + dy*dy) + 1e-12f;
        float cph = dx/rho, sph = dy/rho;
        float P0[7]; P0[0]=1.f; P0[1]=ct;
        #pragma unroll
        for (int l=2;l<=6;l++) P0[l] = ((2*l-1)*ct*P0[l-1] - (l-1)*P0[l-2]) / l;
        float P1[7]; P1[0]=0.f; P1[1]=-rho; P1[2]=-3.f*ct*rho;
        #pragma unroll
        for (int l=3;l<=6;l++) P1[l] = ((2*l-1)*ct*P1[l-1] - l*P1[l-2]) / (l-1);
        float* Yp = &g_Y[e*KH];
        const float FPI = 12.566370614359172f;
        Yp[0] = 0.28209479177387814f;
        int idx = 1;
        #pragma unroll
        for (int l=1;l<=6;l++) {
            float K0 = sqrtf((2*l+1)/FPI);
            float K1 = sqrtf(2.f*(2*l+1)/(FPI*l*(l+1)));
            Yp[idx++] = K1*P1[l]*sph;
            Yp[idx++] = K0*P0[l];
            Yp[idx++] = K1*P1[l]*cph;
        }
    }
    __syncthreads();
    const float step = 8.0f/127.0f;
    const float inv  = 127.0f/8.0f;
    for (int el = 0; el < 32; el++) {
        float d = ds[el];
        float t = (d - step*(float)tid)*inv;
        g_rbf[(e0+el)*NBIN + tid] = expf(-0.5f*t*t);
    }
}

// ---------------- k_s: s[e,c] = sum_k Y[e,k]*x[src[e],k,c]; c-eighths, 2 CTA/SM ----------------
#define XS_F (ATOMS*KH*16)   /* 9728 floats */
#define YS_F (640*KH)        /* 12160 floats */
__global__ __launch_bounds__(256, 2) void k_s(const int* __restrict__ ei) {
    int cq = blockIdx.x;          // 0..7 (16-channel slice)
    int cb = blockIdx.y;          // crystal
    int tid = threadIdx.x;
    extern __shared__ float sm[];
    float* xs  = sm;              // [atom][k][16c]
    float* Ys  = sm + XS_F;       // [640][19]
    int*  srcs = (int*)(Ys + YS_F);
    int abase = cb*ATOMS;
    int c0 = cq*16;
    for (int i = tid; i < XS_F; i += 256) {
        int a = i/(KH*16); int r = i - a*(KH*16); int k = r >> 4; int c = r & 15;
        xs[i] = g_x[((abase+a)*KH + k)*CCH + c0 + c];
    }
    int ebase = cb*640;
    for (int i = tid; i < YS_F; i += 256) Ys[i] = g_Y[ebase*KH + i];
    for (int i = tid; i < 640; i += 256) srcs[i] = ei[ebase + i] - abase;
    __syncthreads();
    int cl = tid & 15, er = tid >> 4;    // 16 edge rows
    for (int j = 0; j < 40; j++) {
        int e = j*16 + er;
        int sl = srcs[e];
        const float* xr = &xs[sl*(KH*16) + cl];
        const float* yr = &Ys[e*KH];
        float a0 = 0.f, a1 = 0.f;
        #pragma unroll
        for (int k = 0; k < 18; k += 2) {
            a0 = fmaf(yr[k],   xr[k*16],      a0);
            a1 = fmaf(yr[k+1], xr[(k+1)*16],  a1);
        }
        a0 = fmaf(yr[18], xr[18*16], a0);
        g_s[(ebase+e)*CCH + c0 + cl] = a0 + a1;
    }
}

// ---------------- k_mlp: h = silu([s|rbf]@[W1;Wd]); m = h@W2  (FFMA2, aT<->hT aliased) ----------------
__global__ __launch_bounds__(256, 2) void k_mlp(const float* __restrict__ W1,
                                                const float* __restrict__ Wd,
                                                const float* __restrict__ W2,
                                                int layer) {
    int tid = threadIdx.x;
    int e0  = blockIdx.x * 64;
    extern __shared__ float sm[];
    float* aT = sm;                  // 64 x 257 : [s|rbf], later silu(h)
    float* wS = sm + 64*257;         // 16 x 256

    for (int i = tid; i < 64*128; i += 256) {
        int r = i >> 7, c = i & 127;
        aT[r*257 + c]       = g_s  [(e0 + r)*CCH  + c];
        aT[r*257 + 128 + c] = g_rbf[(e0 + r)*NBIN + c];
    }
    __syncthreads();

    const int tx = tid & 31, ty = tid >> 5;
    const int h0 = tx*8, r0 = ty*8;

    u64 acc[8][4];
    #pragma unroll
    for (int i = 0; i < 8; i++)
        #pragma unroll
        for (int p = 0; p < 4; p++) acc[i][p] = pack2(0.f, 0.f);

    const float* W1l = W1 + layer*CCH*HID;
    const float* Wdl = Wd + layer*NBIN*HID;

    for (int kk = 0; kk < 256; kk += 16) {
        for (int i = tid; i < 16*256; i += 256) {
            int kr = i >> 8, h = i & 255;
            int k = kk + kr;
            wS[i] = (k < 128) ? W1l[k*HID + h] : Wdl[(k-128)*HID + h];
        }
        __syncthreads();
        #pragma unroll
        for (int k = 0; k < 16; k++) {
            u64 a[8];
            #pragma unroll
            for (int i = 0; i < 8; i++) a[i] = pack_dup(aT[(r0+i)*257 + kk + k]);
            ulonglong2 b01 = *(const ulonglong2*)&wS[k*256 + h0];
            ulonglong2 b23 = *(const ulonglong2*)&wS[k*256 + h0 + 4];
            #pragma unroll
            for (int i = 0; i < 8; i++) {
                ffma2(acc[i][0], a[i], b01.x);
                ffma2(acc[i][1], a[i], b01.y);
                ffma2(acc[i][2], a[i], b23.x);
                ffma2(acc[i][3], a[i], b23.y);
            }
        }
        __syncthreads();
    }

    // silu epilogue written IN PLACE over aT (dead after GEMM1)
    #pragma unroll
    for (int i = 0; i < 8; i++)
        #pragma unroll
        for (int p = 0; p < 4; p++) {
            float v0, v1;
            unpack2(acc[i][p], v0, v1);
            aT[(r0+i)*257 + h0 + 2*p]     = v0 / (1.f + expf(-v0));
            aT[(r0+i)*257 + h0 + 2*p + 1] = v1 / (1.f + expf(-v1));
        }
    __syncthreads();

    const int c0 = tx*4;
    u64 acc2[8][2];
    #pragma unroll
    for (int i = 0; i < 8; i++) { acc2[i][0] = pack2(0.f,0.f); acc2[i][1] = pack2(0.f,0.f); }

    const float* W2l = W2 + layer*HID*CCH;
    for (int kk = 0; kk < 256; kk += 16) {
        for (int i = tid; i < 16*128; i += 256) {
            int kr = i >> 7, c = i & 127;
            wS[i] = W2l[(kk + kr)*CCH + c];
        }
        __syncthreads();
        #pragma unroll
        for (int k = 0; k < 16; k++) {
            ulonglong2 b = *(const ulonglong2*)&wS[k*128 + c0];
            #pragma unroll
            for (int i = 0; i < 8; i++) {
                u64 a = pack_dup(aT[(r0+i)*257 + kk + k]);
                ffma2(acc2[i][0], a, b.x);
                ffma2(acc2[i][1], a, b.y);
            }
        }
        __syncthreads();
    }
    #pragma unroll
    for (int i = 0; i < 8; i++) {
        ulonglong2 o; o.x = acc2[i][0]; o.y = acc2[i][1];
        *(ulonglong2*)&g_m[(e0 + r0 + i)*CCH + c0] = o;
    }
}

// ---------------- k_agg ----------------
__global__ void k_agg() {
    int n = blockIdx.x, tid = threadIdx.x;
    __shared__ float mS[NBR*CCH];
    __shared__ float yS[NBR*KH];
    int eb = n*NBR;
    for (int i = tid; i < NBR*CCH; i += 128) mS[i] = g_m[eb*CCH + i];
    for (int i = tid; i < NBR*KH;  i += 128) yS[i] = g_Y[eb*KH + i];
    __syncthreads();
    int c = tid;
    float acc[KH];
    #pragma unroll
    for (int k = 0; k < KH; k++) acc[k] = 0.f;
    #pragma unroll
    for (int e = 0; e < NBR; e++) {
        float mv = mS[e*CCH + c];
        #pragma unroll
        for (int k = 0; k < KH; k++) acc[k] = fmaf(yS[e*KH + k], mv, acc[k]);
    }
    #pragma unroll
    for (int k = 0; k < KH; k++) g_x[(n*KH + k)*CCH + c] += acc[k]*0.05f;
}

// ---------------- k_hw ----------------
__global__ void k_hw(const float* __restrict__ wf) {
    int n = blockIdx.x, lane = threadIdx.x;
    float v = 0.f;
    for (int c = lane; c < CCH; c += 32) v += g_x[n*(KH*CCH) + c]*wf[c];
    #pragma unroll
    for (int off = 16; off; off >>= 1) v += __shfl_xor_sync(0xffffffffu, v, off);
    if (lane == 0) g_hw[n] = v;
}

// ---------------- k_out ----------------
__global__ void k_out(const float* __restrict__ Wa, const float* __restrict__ ba,
                      const int* __restrict__ ei, float* __restrict__ out) {
    int n = blockIdx.x, tid = threadIdx.x;
    __shared__ float hs[CCH];
    hs[tid] = g_x[n*(KH*CCH) + tid];
    __syncthreads();
    if (tid < 100) {
        float acc = ba[tid];
        for (int c = 0; c < CCH; c++) acc = fmaf(hs[c], Wa[c*100 + tid], acc);
        out[NATOM*3 + n*100 + tid] = acc;
    } else if (tid < 103) {
        int j = tid - 100;
        float hwn = g_hw[n];
        float acc = 0.f;
        for (int e = 0; e < NBR; e++) {
            int ge = n*NBR + e;
            acc = fmaf(g_hw[ei[ge]] - hwn, g_dirn[ge*3 + j], acc);
        }
        out[n*3 + j] = acc;
    }
}

// ---------------- launch ----------------
static const int SMEM_S = (XS_F + YS_F)*4 + 640*4;        // 90112 B
static const int SMEM_M = (64*257 + 16*256) * 4;          // 82176 B

extern "C" void kernel_launch(void* const* d_in, const int* in_sizes, int n_in,
                              void* d_out, int out_size) {
    const float* z       = (const float*)d_in[0];
    const float* frac    = (const float*)d_in[1];
    const int*   types   = (const int*)  d_in[2];
    const float* lengths = (const float*)d_in[4];
    const float* angles  = (const float*)d_in[5];
    const int*   batch   = (const int*)  d_in[6];
    const int*   ei      = (const int*)  d_in[7];
    const float* emb     = (const float*)d_in[8];
    const float* zproj   = (const float*)d_in[9];
    const float* Wd      = (const float*)d_in[10];
    const float* W1      = (const float*)d_in[11];
    const float* W2      = (const float*)d_in[12];
    const float* Wa      = (const float*)d_in[13];
    const float* ba      = (const float*)d_in[14];
    const float* wf      = (const float*)d_in[15];
    float* out = (float*)d_out;

    cudaFuncSetAttribute(k_s,   cudaFuncAttributeMaxDynamicSharedMemorySize, SMEM_S);
    cudaFuncSetAttribute(k_mlp, cudaFuncAttributeMaxDynamicSharedMemorySize, SMEM_M);

    k_prep <<<NCRYST, 128>>>(z, frac, lengths, angles, zproj);
    k_xinit<<<NATOM, 128>>>(types, batch, emb);
    k_edge <<<NEDGE/32, 128>>>(ei);
    for (int l = 0; l < NLAYER; l++) {
        k_s  <<<dim3(8, NCRYST), 256, SMEM_S>>>(ei);
        k_mlp<<<NEDGE/64, 256, SMEM_M>>>(W1, Wd, W2, l);
        k_agg<<<NATOM, 128>>>();
    }
    k_hw <<<NATOM, 32>>>(wf);
    k_out<<<NATOM, 128>>>(Wa, ba, ei, out);
}

// round 5
// speedup vs baseline: 2.0974x; 1.5851x over previous
#include <cuda_runtime.h>
#include <cuda_bf16.h>
#include <math.h>
#include <stdint.h>

#define NCRYST 64
#define ATOMS  32
#define NATOM  2048
#define NBR    20
#define NEDGE  40960
#define CCH    128
#define HID    256
#define NBIN   128
#define NLAYER 8
#define KH     19
#define NCTA_MLP (NEDGE/128)     // 320

typedef unsigned long long u64;
typedef unsigned int u32;

// ---------------- scratch ----------------
__device__ float g_pos [NATOM * 3];
__device__ float g_dirn[NEDGE * 3];
__device__ float g_Y   [NEDGE * KH];
__device__ float g_rbf [NEDGE * NBIN];
__device__ float g_x   [NATOM * KH * CCH];
__device__ float g_s   [NEDGE * CCH];
__device__ float g_m   [NEDGE * CCH];
__device__ float g_zc  [NCRYST * CCH];
__device__ float g_hw  [NATOM];
// fragment-order weight images: [layer][nhalf][chunk][img][1024 uint4]
__device__ uint4 g_w1img[8*2*4*2*1024];          // 2 MB
__device__ uint4 g_w2img[8*4*2*1024];            // 1 MB
// fragment-order A image: [cta 320][chunk 4][img 2][1024 uint4]
__device__ uint4 g_aimg [NCTA_MLP*4*2*1024];     // 40 MB

// ---------------- helpers ----------------
__device__ __forceinline__ void split2(float v0, float v1, u32& hi, u32& lo){
    __nv_bfloat16 h0 = __float2bfloat16_rn(v0);
    __nv_bfloat16 h1 = __float2bfloat16_rn(v1);
    float l0 = v0 - __bfloat162float(h0);
    float l1 = v1 - __bfloat162float(h1);
    __nv_bfloat162 H; H.x = h0; H.y = h1;
    __nv_bfloat162 L = __floats2bfloat162_rn(l0, l1);
    hi = *(u32*)&H; lo = *(u32*)&L;
}

__device__ __forceinline__ void mma16816(float* c, const uint4 a, const u32 b0, const u32 b1){
    asm volatile("mma.sync.aligned.m16n8k16.row.col.f32.bf16.bf16.f32 "
        "{%0,%1,%2,%3}, {%4,%5,%6,%7}, {%8,%9}, {%0,%1,%2,%3};"
        : "+f"(c[0]), "+f"(c[1]), "+f"(c[2]), "+f"(c[3])
        : "r"(a.x), "r"(a.y), "r"(a.z), "r"(a.w), "r"(b0), "r"(b1));
}

// ---------------- k_wconv: bake weights into mma fragment images ----------------
// B-frag (n8 x k16, col): lane t holds b0=(k=(t&3)*2+{0,1}, n=t>>2), b1=(k+8, n).
// uint4 per (kt, npair, lane): {ntEven.b0, ntEven.b1, ntOdd.b0, ntOdd.b1}
__global__ void k_wconv(const float* __restrict__ W1, const float* __restrict__ Wd,
                        const float* __restrict__ W2) {
    int t = blockIdx.x * 256 + threadIdx.x;
    if (t < 65536) {                         // W1cat: 8l x 2nh x 4ch x 1024
        int l  = t >> 13;
        int r  = t & 8191;
        int nh = r >> 12;
        int ch = (r >> 10) & 3;
        int w  = r & 1023;
        int np = w >> 7, ktl = (w >> 5) & 3, lane = w & 31;
        int nE = nh*128 + np*16 + (lane >> 2);
        int nO = nE + 8;
        int k0 = ch*64 + ktl*16 + (lane & 3)*2;
        float v[8];
        #pragma unroll
        for (int q = 0; q < 4; q++) {
            int k = k0 + (q & 1)*8 + 0;        // q: 0->(nE,k0),1->(nE,k0+8),2->(nO,k0),3->(nO,k0+8)
            int n = (q < 2) ? nE : nO;
            int kk = k0 + ((q & 1) ? 8 : 0);
            float a0, a1;
            if (kk < 128) { a0 = W1[l*32768 + kk*256 + n];       a1 = W1[l*32768 + (kk+1)*256 + n]; }
            else          { a0 = Wd[l*32768 + (kk-128)*256 + n]; a1 = Wd[l*32768 + (kk-127)*256 + n]; }
            v[q*2] = a0; v[q*2+1] = a1;
            (void)k;
        }
        uint4 hi, lo;
        split2(v[0], v[1], hi.x, lo.x);
        split2(v[2], v[3], hi.y, lo.y);
        split2(v[4], v[5], hi.z, lo.z);
        split2(v[6], v[7], hi.w, lo.w);
        size_t base = ((size_t)((l*2 + nh)*4 + ch)*2) * 1024 + w;
        g_w1img[base]        = hi;
        g_w1img[base + 1024] = lo;
    } else if (t < 98304) {                  // W2: 8l x 4ch x 1024
        int u  = t - 65536;
        int l  = u >> 12;
        int ch = (u >> 10) & 3;
        int w  = u & 1023;
        int np = w >> 7, ktl = (w >> 5) & 3, lane = w & 31;
        int nE = np*16 + (lane >> 2);
        int nO = nE + 8;
        int k0 = ch*64 + ktl*16 + (lane & 3)*2;
        float v[8];
        #pragma unroll
        for (int q = 0; q < 4; q++) {
            int n = (q < 2) ? nE : nO;
            int kk = k0 + ((q & 1) ? 8 : 0);
            v[q*2]   = W2[l*32768 + kk*128 + n];
            v[q*2+1] = W2[l*32768 + (kk+1)*128 + n];
        }
        uint4 hi, lo;
        split2(v[0], v[1], hi.x, lo.x);
        split2(v[2], v[3], hi.y, lo.y);
        split2(v[4], v[5], hi.z, lo.z);
        split2(v[6], v[7], hi.w, lo.w);
        size_t base = ((size_t)(l*4 + ch)*2) * 1024 + w;
        g_w2img[base]        = hi;
        g_w2img[base + 1024] = lo;
    }
}

// ---------------- k_aprep: bake A (s or rbf part) into fragment images ----------------
// A-frag (m16 x k16, row): lane t: a0=(m=t>>2, k=(t&3)*2+{0,1}), a1=(m+8,k), a2=(m,k+8), a3=(m+8,k+8)
__global__ void k_aprep(int which) {   // 0 = s (chunks 0,1), 1 = rbf (chunks 2,3)
    int t = blockIdx.x * 256 + threadIdx.x;   // 655360 slots
    int cta = t >> 11;
    int r   = t & 2047;
    int chl = r >> 10;
    int w   = r & 1023;
    int mt = w >> 7, ktl = (w >> 5) & 3, lane = w & 31;
    int m0 = mt*16 + (lane >> 2);
    int kk = chl*64 + ktl*16 + (lane & 3)*2;
    const float* src = which ? g_rbf : g_s;
    size_t row0 = (size_t)(cta*128 + m0) * 128;
    size_t row1 = row0 + 8*128;
    float2 p00 = *(const float2*)&src[row0 + kk];
    float2 p10 = *(const float2*)&src[row1 + kk];
    float2 p01 = *(const float2*)&src[row0 + kk + 8];
    float2 p11 = *(const float2*)&src[row1 + kk + 8];
    uint4 hi, lo;
    split2(p00.x, p00.y, hi.x, lo.x);
    split2(p10.x, p10.y, hi.y, lo.y);
    split2(p01.x, p01.y, hi.z, lo.z);
    split2(p11.x, p11.y, hi.w, lo.w);
    int cg = chl + (which ? 2 : 0);
    size_t base = ((size_t)(cta*4 + cg)*2) * 1024 + w;
    g_aimg[base]        = hi;
    g_aimg[base + 1024] = lo;
}

// ---------------- k_prep ----------------
__global__ void k_prep(const float* __restrict__ z, const float* __restrict__ frac,
                       const float* __restrict__ lengths, const float* __restrict__ angles,
                       const float* __restrict__ zproj) {
    int cb = blockIdx.x, tid = threadIdx.x;
    __shared__ float lat[9];
    __shared__ float zs[256];
    if (tid == 0) {
        float a = lengths[cb*3+0], b = lengths[cb*3+1], c = lengths[cb*3+2];
        const float D2R = 0.017453292519943295f;
        float r0 = angles[cb*3+0]*D2R, r1 = angles[cb*3+1]*D2R, r2 = angles[cb*3+2]*D2R;
        float ca = cosf(r0), cbta = cosf(r1), cg = cosf(r2), sg = sinf(r2);
        float v3y = (ca - cbta*cg)/sg;
        float t = 1.0f - cbta*cbta - v3y*v3y;
        if (t < 1e-8f) t = 1e-8f;
        float v3z = sqrtf(t);
        lat[0]=a;        lat[1]=0.f;     lat[2]=0.f;
        lat[3]=b*cg;     lat[4]=b*sg;    lat[5]=0.f;
        lat[6]=c*cbta;   lat[7]=c*v3y;   lat[8]=c*v3z;
    }
    for (int i = tid; i < 256; i += blockDim.x) zs[i] = z[cb*256 + i];
    __syncthreads();
    if (tid < 96) {
        int a = tid/3, j = tid%3;
        int n = cb*ATOMS + a;
        g_pos[n*3+j] = frac[n*3+0]*lat[0+j] + frac[n*3+1]*lat[3+j] + frac[n*3+2]*lat[6+j];
    }
    float acc = 0.f;
    for (int i = 0; i < 256; i++) acc += zs[i]*zproj[i*CCH + tid];
    g_zc[cb*CCH + tid] = acc;
}

// ---------------- k_xinit ----------------
__global__ void k_xinit(const int* __restrict__ types, const int* __restrict__ batch,
                        const float* __restrict__ emb) {
    int n = blockIdx.x, c = threadIdx.x;
    int t = types[n];
    g_x[(n*KH + 0)*CCH + c] = emb[t*CCH + c] + g_zc[batch[n]*CCH + c];
    #pragma unroll
    for (int k = 1; k < KH; k++) g_x[(n*KH + k)*CCH + c] = 0.f;
}

// ---------------- k_edge ----------------
__global__ void k_edge(const int* __restrict__ ei) {
    int tid = threadIdx.x;
    int e0 = blockIdx.x * 32;
    __shared__ float ds[32];
    if (tid < 32) {
        int e = e0 + tid;
        int s = ei[e], d = ei[NEDGE + e];
        float vx = g_pos[s*3+0]-g_pos[d*3+0];
        float vy = g_pos[s*3+1]-g_pos[d*3+1];
        float vz = g_pos[s*3+2]-g_pos[d*3+2];
        float dist = sqrtf(vx*vx + vy*vy + vz*vz) + 1e-8f;
        ds[tid] = dist;
        float dx = vx/dist, dy = vy/dist, dz = vz/dist;
        g_dirn[e*3+0]=dx; g_dirn[e*3+1]=dy; g_dirn[e*3+2]=dz;
        float ct = dz;
        float rho = sqrtf(dx*dx + dy*dy) + 1e-12f;
        float cph = dx/rho, sph = dy/rho;
        float P0[7]; P0[0]=1.f; P0[1]=ct;
        #pragma unroll
        for (int l=2;l<=6;l++) P0[l] = ((2*l-1)*ct*P0[l-1] - (l-1)*P0[l-2]) / l;
        float P1[7]; P1[0]=0.f; P1[1]=-rho; P1[2]=-3.f*ct*rho;
        #pragma unroll
        for (int l=3;l<=6;l++) P1[l] = ((2*l-1)*ct*P1[l-1] - l*P1[l-2]) / (l-1);
        float* Yp = &g_Y[e*KH];
        const float FPI = 12.566370614359172f;
        Yp[0] = 0.28209479177387814f;
        int idx = 1;
        #pragma unroll
        for (int l=1;l<=6;l++) {
            float K0 = sqrtf((2*l+1)/FPI);
            float K1 = sqrtf(2.f*(2*l+1)/(FPI*l*(l+1)));
            Yp[idx++] = K1*P1[l]*sph;
            Yp[idx++] = K0*P0[l];
            Yp[idx++] = K1*P1[l]*cph;
        }
    }
    __syncthreads();
    const float step = 8.0f/127.0f;
    const float inv  = 127.0f/8.0f;
    for (int el = 0; el < 32; el++) {
        float d = ds[el];
        float t = (d - step*(float)tid)*inv;
        g_rbf[(e0+el)*NBIN + tid] = expf(-0.5f*t*t);
    }
}

// ---------------- k_s (unchanged, known-good) ----------------
#define XS_F (ATOMS*KH*16)
#define YS_F (640*KH)
__global__ __launch_bounds__(256, 2) void k_s(const int* __restrict__ ei) {
    int cq = blockIdx.x;
    int cb = blockIdx.y;
    int tid = threadIdx.x;
    extern __shared__ float sm[];
    float* xs  = sm;
    float* Ys  = sm + XS_F;
    int*  srcs = (int*)(Ys + YS_F);
    int abase = cb*ATOMS;
    int c0 = cq*16;
    for (int i = tid; i < XS_F; i += 256) {
        int a = i/(KH*16); int r = i - a*(KH*16); int k = r >> 4; int c = r & 15;
        xs[i] = g_x[((abase+a)*KH + k)*CCH + c0 + c];
    }
    int ebase = cb*640;
    for (int i = tid; i < YS_F; i += 256) Ys[i] = g_Y[ebase*KH + i];
    for (int i = tid; i < 640; i += 256) srcs[i] = ei[ebase + i] - abase;
    __syncthreads();
    int cl = tid & 15, er = tid >> 4;
    for (int j = 0; j < 40; j++) {
        int e = j*16 + er;
        int sl = srcs[e];
        const float* xr = &xs[sl*(KH*16) + cl];
        const float* yr = &Ys[e*KH];
        float a0 = 0.f, a1 = 0.f;
        #pragma unroll
        for (int k = 0; k < 18; k += 2) {
            a0 = fmaf(yr[k],   xr[k*16],      a0);
            a1 = fmaf(yr[k+1], xr[(k+1)*16],  a1);
        }
        a0 = fmaf(yr[18], xr[18*16], a0);
        g_s[(ebase+e)*CCH + c0 + cl] = a0 + a1;
    }
}

// ---------------- k_mlp: mma.sync bf16 3-pass, fragment layouts ----------------
#define HS_U4    8192            /* h image: 2 img x 4096 uint4 = 128 KB */
#define ABUF_OFF (HS_U4*16)      /* 131072 */
#define BBUF_OFF (ABUF_OFF + 32768)
#define SM_MLP   (BBUF_OFF + 32768)   /* 196608 */

__global__ __launch_bounds__(256, 1) void k_mlp(int layer) {
    extern __shared__ char smem[];
    uint4* hs4  = (uint4*)smem;                    // [img][mt16(8)*kt(16)][lane] : (mt*16+kt)*32+lane
    uint4* sA   = (uint4*)(smem + ABUF_OFF);       // [img][ (mt*4+ktl)*32+lane ]
    uint4* sB   = (uint4*)(smem + BBUF_OFF);       // [img][ (np*4+ktl)*32+lane ]
    u32*   hsw  = (u32*)smem;

    int tid = threadIdx.x;
    int wid = tid >> 5, lane = tid & 31;
    int mw = wid & 3, nw = wid >> 2;
    int cta = blockIdx.x;
    int e0 = cta * 128;

    int g  = lane >> 2;          // 0..7
    int tg = lane & 3;           // 0..3

    // ===================== GEMM1: h = silu([s|rbf] @ W1cat) =====================
    for (int nhalf = 0; nhalf < 2; nhalf++) {
        float acc[2][8][4];
        #pragma unroll
        for (int i = 0; i < 2; i++)
            #pragma unroll
            for (int j = 0; j < 8; j++)
                #pragma unroll
                for (int q = 0; q < 4; q++) acc[i][j][q] = 0.f;

        for (int ch = 0; ch < 4; ch++) {
            __syncthreads();
            {
                const uint4* gA = g_aimg  + ((size_t)(cta*4 + ch)*2) * 1024;
                const uint4* gB = g_w1img + ((size_t)((layer*2 + nhalf)*4 + ch)*2) * 1024;
                #pragma unroll
                for (int i = 0; i < 8; i++) sA[tid + i*256] = gA[tid + i*256];
                #pragma unroll
                for (int i = 0; i < 8; i++) sB[tid + i*256] = gB[tid + i*256];
            }
            __syncthreads();

            for (int kt = 0; kt < 4; kt++) {
                uint4 aH[2], aL[2];
                #pragma unroll
                for (int s = 0; s < 2; s++) {
                    int idx = ((mw*2 + s)*4 + kt)*32 + lane;
                    aH[s] = sA[idx];
                    aL[s] = sA[1024 + idx];
                }
                uint4 bH[4], bL[4];
                #pragma unroll
                for (int j = 0; j < 4; j++) {
                    int idx = ((nw*4 + j)*4 + kt)*32 + lane;
                    bH[j] = sB[idx];
                    bL[j] = sB[1024 + idx];
                }
                #pragma unroll
                for (int j = 0; j < 4; j++)
                    #pragma unroll
                    for (int s = 0; s < 2; s++) {
                        mma16816(acc[s][2*j],   aH[s], bH[j].x, bH[j].y);
                        mma16816(acc[s][2*j+1], aH[s], bH[j].z, bH[j].w);
                        mma16816(acc[s][2*j],   aH[s], bL[j].x, bL[j].y);
                        mma16816(acc[s][2*j+1], aH[s], bL[j].z, bL[j].w);
                        mma16816(acc[s][2*j],   aL[s], bH[j].x, bH[j].y);
                        mma16816(acc[s][2*j+1], aL[s], bH[j].z, bH[j].w);
                    }
            }
        }

        // epilogue: silu + split -> write h fragments (GEMM2 A layout)
        #pragma unroll
        for (int s = 0; s < 2; s++)
            #pragma unroll
            for (int nt = 0; nt < 8; nt++) {
                float c0 = acc[s][nt][0], c1 = acc[s][nt][1];
                float c2 = acc[s][nt][2], c3 = acc[s][nt][3];
                c0 = c0 / (1.f + __expf(-c0));
                c1 = c1 / (1.f + __expf(-c1));
                c2 = c2 / (1.f + __expf(-c2));
                c3 = c3 / (1.f + __expf(-c3));
                int R = mw*32 + s*16 + g;
                int C = nhalf*128 + nw*64 + nt*8 + tg*2;
                u32 hi01, lo01, hi23, lo23;
                split2(c0, c1, hi01, lo01);
                split2(c2, c3, hi23, lo23);
                int mtp  = R >> 4;
                int ktp  = C >> 4;
                int khal = (C >> 3) & 1;
                int lanep = g*4 + tg;          // R&15 = g < 8 always here
                u32 base = (((u32)(mtp*16 + ktp)*32 + lanep) << 2);
                hsw[base + 2*khal]                 = hi01;   // row R   (wsel bit0=0)
                hsw[base + 2*khal + 1]             = hi23;   // row R+8 (wsel bit0=1)
                hsw[16384 + base + 2*khal]         = lo01;   // lo image (+4096 uint4)
                hsw[16384 + base + 2*khal + 1]     = lo23;
            }
    }

    // ===================== GEMM2: m = h @ W2 =====================
    float acc2[2][8][4];
    #pragma unroll
    for (int i = 0; i < 2; i++)
        #pragma unroll
        for (int j = 0; j < 8; j++)
            #pragma unroll
            for (int q = 0; q < 4; q++) acc2[i][j][q] = 0.f;

    for (int ch = 0; ch < 4; ch++) {
        __syncthreads();
        {
            const uint4* gB = g_w2img + ((size_t)(layer*4 + ch)*2) * 1024;
            #pragma unroll
            for (int i = 0; i < 8; i++) sB[tid + i*256] = gB[tid + i*256];
        }
        __syncthreads();

        for (int kt = 0; kt < 4; kt++) {
            int ktg = ch*4 + kt;
            uint4 aH[2], aL[2];
            #pragma unroll
            for (int s = 0; s < 2; s++) {
                int idx = ((mw*2 + s)*16 + ktg)*32 + lane;
                aH[s] = hs4[idx];
                aL[s] = hs4[4096 + idx];
            }
            uint4 bH[4], bL[4];
            #pragma unroll
            for (int j = 0; j < 4; j++) {
                int idx = ((nw*4 + j)*4 + kt)*32 + lane;
                bH[j] = sB[idx];
                bL[j] = sB[1024 + idx];
            }
            #pragma unroll
            for (int j = 0; j < 4; j++)
                #pragma unroll
                for (int s = 0; s < 2; s++) {
                    mma16816(acc2[s][2*j],   aH[s], bH[j].x, bH[j].y);
                    mma16816(acc2[s][2*j+1], aH[s], bH[j].z, bH[j].w);
                    mma16816(acc2[s][2*j],   aH[s], bL[j].x, bL[j].y);
                    mma16816(acc2[s][2*j+1], aH[s], bL[j].z, bL[j].w);
                    mma16816(acc2[s][2*j],   aL[s], bH[j].x, bH[j].y);
                    mma16816(acc2[s][2*j+1], aL[s], bH[j].z, bH[j].w);
                }
        }
    }

    // epilogue: store m
    #pragma unroll
    for (int s = 0; s < 2; s++)
        #pragma unroll
        for (int nt = 0; nt < 8; nt++) {
            int R = mw*32 + s*16 + g;
            int C = nw*64 + nt*8 + tg*2;
            float2 v0 = make_float2(acc2[s][nt][0], acc2[s][nt][1]);
            float2 v1 = make_float2(acc2[s][nt][2], acc2[s][nt][3]);
            *(float2*)&g_m[(size_t)(e0 + R)*CCH + C]     = v0;
            *(float2*)&g_m[(size_t)(e0 + R + 8)*CCH + C] = v1;
        }
}

// ---------------- k_agg ----------------
__global__ void k_agg() {
    int n = blockIdx.x, tid = threadIdx.x;
    __shared__ float mS[NBR*CCH];
    __shared__ float yS[NBR*KH];
    int eb = n*NBR;
    for (int i = tid; i < NBR*CCH; i += 128) mS[i] = g_m[eb*CCH + i];
    for (int i = tid; i < NBR*KH;  i += 128) yS[i] = g_Y[eb*KH + i];
    __syncthreads();
    int c = tid;
    float acc[KH];
    #pragma unroll
    for (int k = 0; k < KH; k++) acc[k] = 0.f;
    #pragma unroll
    for (int e = 0; e < NBR; e++) {
        float mv = mS[e*CCH + c];
        #pragma unroll
        for (int k = 0; k < KH; k++) acc[k] = fmaf(yS[e*KH + k], mv, acc[k]);
    }
    #pragma unroll
    for (int k = 0; k < KH; k++) g_x[(n*KH + k)*CCH + c] += acc[k]*0.05f;
}

// ---------------- k_hw ----------------
__global__ void k_hw(const float* __restrict__ wf) {
    int n = blockIdx.x, lane = threadIdx.x;
    float v = 0.f;
    for (int c = lane; c < CCH; c += 32) v += g_x[n*(KH*CCH) + c]*wf[c];
    #pragma unroll
    for (int off = 16; off; off >>= 1) v += __shfl_xor_sync(0xffffffffu, v, off);
    if (lane == 0) g_hw[n] = v;
}

// ---------------- k_out ----------------
__global__ void k_out(const float* __restrict__ Wa, const float* __restrict__ ba,
                      const int* __restrict__ ei, float* __restrict__ out) {
    int n = blockIdx.x, tid = threadIdx.x;
    __shared__ float hs[CCH];
    hs[tid] = g_x[n*(KH*CCH) + tid];
    __syncthreads();
    if (tid < 100) {
        float acc = ba[tid];
        for (int c = 0; c < CCH; c++) acc = fmaf(hs[c], Wa[c*100 + tid], acc);
        out[NATOM*3 + n*100 + tid] = acc;
    } else if (tid < 103) {
        int j = tid - 100;
        float hwn = g_hw[n];
        float acc = 0.f;
        for (int e = 0; e < NBR; e++) {
            int ge = n*NBR + e;
            acc = fmaf(g_hw[ei[ge]] - hwn, g_dirn[ge*3 + j], acc);
        }
        out[n*3 + j] = acc;
    }
}

// ---------------- launch ----------------
static const int SMEM_S = (XS_F + YS_F)*4 + 640*4;

extern "C" void kernel_launch(void* const* d_in, const int* in_sizes, int n_in,
                              void* d_out, int out_size) {
    const float* z       = (const float*)d_in[0];
    const float* frac    = (const float*)d_in[1];
    const int*   types   = (const int*)  d_in[2];
    const float* lengths = (const float*)d_in[4];
    const float* angles  = (const float*)d_in[5];
    const int*   batch   = (const int*)  d_in[6];
    const int*   ei      = (const int*)  d_in[7];
    const float* emb     = (const float*)d_in[8];
    const float* zproj   = (const float*)d_in[9];
    const float* Wd      = (const float*)d_in[10];
    const float* W1      = (const float*)d_in[11];
    const float* W2      = (const float*)d_in[12];
    const float* Wa      = (const float*)d_in[13];
    const float* ba      = (const float*)d_in[14];
    const float* wf      = (const float*)d_in[15];
    float* out = (float*)d_out;

    cudaFuncSetAttribute(k_s,   cudaFuncAttributeMaxDynamicSharedMemorySize, SMEM_S);
    cudaFuncSetAttribute(k_mlp, cudaFuncAttributeMaxDynamicSharedMemorySize, SM_MLP);

    k_wconv<<<384, 256>>>(W1, Wd, W2);
    k_prep <<<NCRYST, 128>>>(z, frac, lengths, angles, zproj);
    k_xinit<<<NATOM, 128>>>(types, batch, emb);
    k_edge <<<NEDGE/32, 128>>>(ei);
    k_aprep<<<2560, 256>>>(1);               // rbf chunks (2,3), once
    for (int l = 0; l < NLAYER; l++) {
        k_s    <<<dim3(8, NCRYST), 256, SMEM_S>>>(ei);
        k_aprep<<<2560, 256>>>(0);           // s chunks (0,1)
        k_mlp  <<<NCTA_MLP, 256, SM_MLP>>>(l);
        k_agg  <<<NATOM, 128>>>();
    }
    k_hw <<<NATOM, 32>>>(wf);
    k_out<<<NATOM, 128>>>(Wa, ba, ei, out);
}

// round 6
// speedup vs baseline: 2.1113x; 1.0066x over previous
#include <cuda_runtime.h>
#include <cuda_bf16.h>
#include <math.h>
#include <stdint.h>

#define NCRYST 64
#define ATOMS  32
#define NATOM  2048
#define NBR    20
#define NEDGE  40960
#define CCH    128
#define HID    256
#define NBIN   128
#define NLAYER 8
#define KH     19
#define NCTA_MLP (NEDGE/128)     // 320

typedef unsigned long long u64;
typedef unsigned int u32;

// ---------------- scratch ----------------
__device__ float g_pos [NATOM * 3];
__device__ float g_dirn[NEDGE * 3];
__device__ float g_Y   [NEDGE * KH];
__device__ float g_rbf [NEDGE * NBIN];
__device__ float g_x   [NATOM * KH * CCH];
__device__ float g_s   [NEDGE * CCH];
__device__ float g_m   [NEDGE * CCH];
__device__ float g_zc  [NCRYST * CCH];
__device__ float g_hw  [NATOM];
// fragment-order weight images: [layer][nhalf][chunk][img][1024 uint4]
__device__ uint4 g_w1img[8*2*4*2*1024];          // 2 MB
__device__ uint4 g_w2img[8*4*2*1024];            // 1 MB
// fragment-order A image (rbf chunks 2,3 only used now): [cta][chunk 4][img 2][1024 uint4]
__device__ uint4 g_aimg [NCTA_MLP*4*2*1024];     // 40 MB

// ---------------- helpers ----------------
__device__ __forceinline__ void split2(float v0, float v1, u32& hi, u32& lo){
    __nv_bfloat16 h0 = __float2bfloat16_rn(v0);
    __nv_bfloat16 h1 = __float2bfloat16_rn(v1);
    float l0 = v0 - __bfloat162float(h0);
    float l1 = v1 - __bfloat162float(h1);
    __nv_bfloat162 H; H.x = h0; H.y = h1;
    __nv_bfloat162 L = __floats2bfloat162_rn(l0, l1);
    hi = *(u32*)&H; lo = *(u32*)&L;
}

__device__ __forceinline__ void mma16816(float* c, const uint4 a, const u32 b0, const u32 b1){
    asm volatile("mma.sync.aligned.m16n8k16.row.col.f32.bf16.bf16.f32 "
        "{%0,%1,%2,%3}, {%4,%5,%6,%7}, {%8,%9}, {%0,%1,%2,%3};"
        : "+f"(c[0]), "+f"(c[1]), "+f"(c[2]), "+f"(c[3])
        : "r"(a.x), "r"(a.y), "r"(a.z), "r"(a.w), "r"(b0), "r"(b1));
}

// ---------------- k_wconv ----------------
__global__ void k_wconv(const float* __restrict__ W1, const float* __restrict__ Wd,
                        const float* __restrict__ W2) {
    int t = blockIdx.x * 256 + threadIdx.x;
    if (t < 65536) {                         // W1cat: 8l x 2nh x 4ch x 1024
        int l  = t >> 13;
        int r  = t & 8191;
        int nh = r >> 12;
        int ch = (r >> 10) & 3;
        int w  = r & 1023;
        int np = w >> 7, ktl = (w >> 5) & 3, lane = w & 31;
        int nE = nh*128 + np*16 + (lane >> 2);
        int nO = nE + 8;
        int k0 = ch*64 + ktl*16 + (lane & 3)*2;
        float v[8];
        #pragma unroll
        for (int q = 0; q < 4; q++) {
            int n = (q < 2) ? nE : nO;
            int kk = k0 + ((q & 1) ? 8 : 0);
            float a0, a1;
            if (kk < 128) { a0 = W1[l*32768 + kk*256 + n];       a1 = W1[l*32768 + (kk+1)*256 + n]; }
            else          { a0 = Wd[l*32768 + (kk-128)*256 + n]; a1 = Wd[l*32768 + (kk-127)*256 + n]; }
            v[q*2] = a0; v[q*2+1] = a1;
        }
        uint4 hi, lo;
        split2(v[0], v[1], hi.x, lo.x);
        split2(v[2], v[3], hi.y, lo.y);
        split2(v[4], v[5], hi.z, lo.z);
        split2(v[6], v[7], hi.w, lo.w);
        size_t base = ((size_t)((l*2 + nh)*4 + ch)*2) * 1024 + w;
        g_w1img[base]        = hi;
        g_w1img[base + 1024] = lo;
    } else if (t < 98304) {                  // W2: 8l x 4ch x 1024
        int u  = t - 65536;
        int l  = u >> 12;
        int ch = (u >> 10) & 3;
        int w  = u & 1023;
        int np = w >> 7, ktl = (w >> 5) & 3, lane = w & 31;
        int nE = np*16 + (lane >> 2);
        int nO = nE + 8;
        int k0 = ch*64 + ktl*16 + (lane & 3)*2;
        float v[8];
        #pragma unroll
        for (int q = 0; q < 4; q++) {
            int n = (q < 2) ? nE : nO;
            int kk = k0 + ((q & 1) ? 8 : 0);
            v[q*2]   = W2[l*32768 + kk*128 + n];
            v[q*2+1] = W2[l*32768 + (kk+1)*128 + n];
        }
        uint4 hi, lo;
        split2(v[0], v[1], hi.x, lo.x);
        split2(v[2], v[3], hi.y, lo.y);
        split2(v[4], v[5], hi.z, lo.z);
        split2(v[6], v[7], hi.w, lo.w);
        size_t base = ((size_t)(l*4 + ch)*2) * 1024 + w;
        g_w2img[base]        = hi;
        g_w2img[base + 1024] = lo;
    }
}

// ---------------- k_aprep: bake rbf fragment images (once) ----------------
__global__ void k_aprep() {
    int t = blockIdx.x * 256 + threadIdx.x;   // 655360 slots
    int cta = t >> 11;
    int r   = t & 2047;
    int chl = r >> 10;
    int w   = r & 1023;
    int mt = w >> 7, ktl = (w >> 5) & 3, lane = w & 31;
    int m0 = mt*16 + (lane >> 2);
    int kk = chl*64 + ktl*16 + (lane & 3)*2;
    size_t row0 = (size_t)(cta*128 + m0) * 128;
    size_t row1 = row0 + 8*128;
    float2 p00 = *(const float2*)&g_rbf[row0 + kk];
    float2 p10 = *(const float2*)&g_rbf[row1 + kk];
    float2 p01 = *(const float2*)&g_rbf[row0 + kk + 8];
    float2 p11 = *(const float2*)&g_rbf[row1 + kk + 8];
    uint4 hi, lo;
    split2(p00.x, p00.y, hi.x, lo.x);
    split2(p10.x, p10.y, hi.y, lo.y);
    split2(p01.x, p01.y, hi.z, lo.z);
    split2(p11.x, p11.y, hi.w, lo.w);
    int cg = chl + 2;
    size_t base = ((size_t)(cta*4 + cg)*2) * 1024 + w;
    g_aimg[base]        = hi;
    g_aimg[base + 1024] = lo;
}

// ---------------- k_prep ----------------
__global__ void k_prep(const float* __restrict__ z, const float* __restrict__ frac,
                       const float* __restrict__ lengths, const float* __restrict__ angles,
                       const float* __restrict__ zproj) {
    int cb = blockIdx.x, tid = threadIdx.x;
    __shared__ float lat[9];
    __shared__ float zs[256];
    if (tid == 0) {
        float a = lengths[cb*3+0], b = lengths[cb*3+1], c = lengths[cb*3+2];
        const float D2R = 0.017453292519943295f;
        float r0 = angles[cb*3+0]*D2R, r1 = angles[cb*3+1]*D2R, r2 = angles[cb*3+2]*D2R;
        float ca = cosf(r0), cbta = cosf(r1), cg = cosf(r2), sg = sinf(r2);
        float v3y = (ca - cbta*cg)/sg;
        float t = 1.0f - cbta*cbta - v3y*v3y;
        if (t < 1e-8f) t = 1e-8f;
        float v3z = sqrtf(t);
        lat[0]=a;        lat[1]=0.f;     lat[2]=0.f;
        lat[3]=b*cg;     lat[4]=b*sg;    lat[5]=0.f;
        lat[6]=c*cbta;   lat[7]=c*v3y;   lat[8]=c*v3z;
    }
    for (int i = tid; i < 256; i += blockDim.x) zs[i] = z[cb*256 + i];
    __syncthreads();
    if (tid < 96) {
        int a = tid/3, j = tid%3;
        int n = cb*ATOMS + a;
        g_pos[n*3+j] = frac[n*3+0]*lat[0+j] + frac[n*3+1]*lat[3+j] + frac[n*3+2]*lat[6+j];
    }
    float acc = 0.f;
    for (int i = 0; i < 256; i++) acc += zs[i]*zproj[i*CCH + tid];
    g_zc[cb*CCH + tid] = acc;
}

// ---------------- k_xinit ----------------
__global__ void k_xinit(const int* __restrict__ types, const int* __restrict__ batch,
                        const float* __restrict__ emb) {
    int n = blockIdx.x, c = threadIdx.x;
    int t = types[n];
    g_x[(n*KH + 0)*CCH + c] = emb[t*CCH + c] + g_zc[batch[n]*CCH + c];
    #pragma unroll
    for (int k = 1; k < KH; k++) g_x[(n*KH + k)*CCH + c] = 0.f;
}

// ---------------- k_edge ----------------
__global__ void k_edge(const int* __restrict__ ei) {
    int tid = threadIdx.x;
    int e0 = blockIdx.x * 32;
    __shared__ float ds[32];
    if (tid < 32) {
        int e = e0 + tid;
        int s = ei[e], d = ei[NEDGE + e];
        float vx = g_pos[s*3+0]-g_pos[d*3+0];
        float vy = g_pos[s*3+1]-g_pos[d*3+1];
        float vz = g_pos[s*3+2]-g_pos[d*3+2];
        float dist = sqrtf(vx*vx + vy*vy + vz*vz) + 1e-8f;
        ds[tid] = dist;
        float dx = vx/dist, dy = vy/dist, dz = vz/dist;
        g_dirn[e*3+0]=dx; g_dirn[e*3+1]=dy; g_dirn[e*3+2]=dz;
        float ct = dz;
        float rho = sqrtf(dx*dx + dy*dy) + 1e-12f;
        float cph = dx/rho, sph = dy/rho;
        float P0[7]; P0[0]=1.f; P0[1]=ct;
        #pragma unroll
        for (int l=2;l<=6;l++) P0[l] = ((2*l-1)*ct*P0[l-1] - (l-1)*P0[l-2]) / l;
        float P1[7]; P1[0]=0.f; P1[1]=-rho; P1[2]=-3.f*ct*rho;
        #pragma unroll
        for (int l=3;l<=6;l++) P1[l] = ((2*l-1)*ct*P1[l-1] - l*P1[l-2]) / (l-1);
        float* Yp = &g_Y[e*KH];
        const float FPI = 12.566370614359172f;
        Yp[0] = 0.28209479177387814f;
        int idx = 1;
        #pragma unroll
        for (int l=1;l<=6;l++) {
            float K0 = sqrtf((2*l+1)/FPI);
            float K1 = sqrtf(2.f*(2*l+1)/(FPI*l*(l+1)));
            Yp[idx++] = K1*P1[l]*sph;
            Yp[idx++] = K0*P0[l];
            Yp[idx++] = K1*P1[l]*cph;
        }
    }
    __syncthreads();
    const float step = 8.0f/127.0f;
    const float inv  = 127.0f/8.0f;
    for (int el = 0; el < 32; el++) {
        float d = ds[el];
        float t = (d - step*(float)tid)*inv;
        g_rbf[(e0+el)*NBIN + tid] = expf(-0.5f*t*t);
    }
}

// ---------------- k_s: float4 channels, padded smem stride ----------------
#define XS_STRIDE 20
#define XS_F (ATOMS*KH*XS_STRIDE)   /* 12160 */
#define YS_F (640*KH)               /* 12160 */
__global__ __launch_bounds__(256, 2) void k_s(const int* __restrict__ ei) {
    int cq = blockIdx.x;          // 0..7 (16-channel slice)
    int cb = blockIdx.y;
    int tid = threadIdx.x;
    extern __shared__ float sm[];
    float* xs  = sm;              // [atom][k] stride 20, 16 channels used
    float* Ys  = sm + XS_F;
    int*  srcs = (int*)(Ys + YS_F);
    int abase = cb*ATOMS;
    int c0 = cq*16;
    for (int i = tid; i < ATOMS*KH*16; i += 256) {
        int a = i/(KH*16); int r = i - a*(KH*16); int k = r >> 4; int c = r & 15;
        xs[(a*KH + k)*XS_STRIDE + c] = g_x[((abase+a)*KH + k)*CCH + c0 + c];
    }
    int ebase = cb*640;
    for (int i = tid; i < YS_F; i += 256) Ys[i] = g_Y[ebase*KH + i];
    for (int i = tid; i < 640; i += 256) srcs[i] = ei[ebase + i] - abase;
    __syncthreads();
    int cg = tid & 3, er = tid >> 2;     // 4 channel-groups x 64 edge rows
    #pragma unroll 2
    for (int j = 0; j < 10; j++) {
        int e = j*64 + er;
        int sl = srcs[e];
        const float* xr = &xs[sl*(KH*XS_STRIDE) + cg*4];
        const float* yr = &Ys[e*KH];
        float4 acc = make_float4(0.f, 0.f, 0.f, 0.f);
        #pragma unroll
        for (int k = 0; k < KH; k++) {
            float y = yr[k];
            float4 xv = *(const float4*)&xr[k*XS_STRIDE];
            acc.x = fmaf(y, xv.x, acc.x);
            acc.y = fmaf(y, xv.y, acc.y);
            acc.z = fmaf(y, xv.z, acc.z);
            acc.w = fmaf(y, xv.w, acc.w);
        }
        *(float4*)&g_s[(size_t)(ebase+e)*CCH + c0 + cg*4] = acc;
    }
}

// ---------------- k_mlp: mma.sync bf16 3-pass; s-frags built in-kernel ----------------
#define HS_U4    8192
#define ABUF_OFF (HS_U4*16)      /* 131072 */
#define BBUF_OFF (ABUF_OFF + 32768)
#define SM_MLP   (BBUF_OFF + 32768)   /* 196608 */

__global__ __launch_bounds__(256, 1) void k_mlp(int layer) {
    extern __shared__ char smem[];
    uint4* hs4  = (uint4*)smem;
    uint4* sA   = (uint4*)(smem + ABUF_OFF);
    uint4* sB   = (uint4*)(smem + BBUF_OFF);
    u32*   hsw  = (u32*)smem;

    int tid = threadIdx.x;
    int wid = tid >> 5, lane = tid & 31;
    int mw = wid & 3, nw = wid >> 2;
    int cta = blockIdx.x;
    int e0 = cta * 128;

    int g  = lane >> 2;
    int tg = lane & 3;

    // ===================== GEMM1 =====================
    for (int nhalf = 0; nhalf < 2; nhalf++) {
        float acc[2][8][4];
        #pragma unroll
        for (int i = 0; i < 2; i++)
            #pragma unroll
            for (int j = 0; j < 8; j++)
                #pragma unroll
                for (int q = 0; q < 4; q++) acc[i][j][q] = 0.f;

        for (int ch = 0; ch < 4; ch++) {
            __syncthreads();
            if (ch < 2) {
                // build s-chunk A-fragments directly from g_s
                #pragma unroll
                for (int i = 0; i < 4; i++) {
                    int w = tid + i*256;
                    int mt = w >> 7, ktl = (w >> 5) & 3, ln = w & 31;
                    int m0 = mt*16 + (ln >> 2);
                    int kk = ch*64 + ktl*16 + (ln & 3)*2;
                    size_t row0 = (size_t)(e0 + m0)*CCH;
                    size_t row1 = row0 + 8*CCH;
                    float2 p00 = *(const float2*)&g_s[row0 + kk];
                    float2 p10 = *(const float2*)&g_s[row1 + kk];
                    float2 p01 = *(const float2*)&g_s[row0 + kk + 8];
                    float2 p11 = *(const float2*)&g_s[row1 + kk + 8];
                    uint4 hi, lo;
                    split2(p00.x, p00.y, hi.x, lo.x);
                    split2(p10.x, p10.y, hi.y, lo.y);
                    split2(p01.x, p01.y, hi.z, lo.z);
                    split2(p11.x, p11.y, hi.w, lo.w);
                    sA[w]        = hi;
                    sA[1024 + w] = lo;
                }
            } else {
                const uint4* gA = g_aimg + ((size_t)(cta*4 + ch)*2) * 1024;
                #pragma unroll
                for (int i = 0; i < 8; i++) sA[tid + i*256] = gA[tid + i*256];
            }
            {
                const uint4* gB = g_w1img + ((size_t)((layer*2 + nhalf)*4 + ch)*2) * 1024;
                #pragma unroll
                for (int i = 0; i < 8; i++) sB[tid + i*256] = gB[tid + i*256];
            }
            __syncthreads();

            for (int kt = 0; kt < 4; kt++) {
                uint4 aH[2], aL[2];
                #pragma unroll
                for (int s = 0; s < 2; s++) {
                    int idx = ((mw*2 + s)*4 + kt)*32 + lane;
                    aH[s] = sA[idx];
                    aL[s] = sA[1024 + idx];
                }
                uint4 bH[4], bL[4];
                #pragma unroll
                for (int j = 0; j < 4; j++) {
                    int idx = ((nw*4 + j)*4 + kt)*32 + lane;
                    bH[j] = sB[idx];
                    bL[j] = sB[1024 + idx];
                }
                #pragma unroll
                for (int j = 0; j < 4; j++)
                    #pragma unroll
                    for (int s = 0; s < 2; s++) {
                        mma16816(acc[s][2*j],   aH[s], bH[j].x, bH[j].y);
                        mma16816(acc[s][2*j+1], aH[s], bH[j].z, bH[j].w);
                        mma16816(acc[s][2*j],   aH[s], bL[j].x, bL[j].y);
                        mma16816(acc[s][2*j+1], aH[s], bL[j].z, bL[j].w);
                        mma16816(acc[s][2*j],   aL[s], bH[j].x, bH[j].y);
                        mma16816(acc[s][2*j+1], aL[s], bH[j].z, bH[j].w);
                    }
            }
        }

        // epilogue: silu + split -> h fragments in smem (GEMM2 A layout)
        #pragma unroll
        for (int s = 0; s < 2; s++)
            #pragma unroll
            for (int nt = 0; nt < 8; nt++) {
                float c0 = acc[s][nt][0], c1 = acc[s][nt][1];
                float c2 = acc[s][nt][2], c3 = acc[s][nt][3];
                c0 = c0 / (1.f + __expf(-c0));
                c1 = c1 / (1.f + __expf(-c1));
                c2 = c2 / (1.f + __expf(-c2));
                c3 = c3 / (1.f + __expf(-c3));
                int R = mw*32 + s*16 + g;
                int C = nhalf*128 + nw*64 + nt*8 + tg*2;
                u32 hi01, lo01, hi23, lo23;
                split2(c0, c1, hi01, lo01);
                split2(c2, c3, hi23, lo23);
                int mtp  = R >> 4;
                int ktp  = C >> 4;
                int khal = (C >> 3) & 1;
                int lanep = g*4 + tg;
                u32 base = (((u32)(mtp*16 + ktp)*32 + lanep) << 2);
                hsw[base + 2*khal]             = hi01;
                hsw[base + 2*khal + 1]         = hi23;
                hsw[16384 + base + 2*khal]     = lo01;
                hsw[16384 + base + 2*khal + 1] = lo23;
            }
    }

    // ===================== GEMM2 =====================
    float acc2[2][8][4];
    #pragma unroll
    for (int i = 0; i < 2; i++)
        #pragma unroll
        for (int j = 0; j < 8; j++)
            #pragma unroll
            for (int q = 0; q < 4; q++) acc2[i][j][q] = 0.f;

    for (int ch = 0; ch < 4; ch++) {
        __syncthreads();
        {
            const uint4* gB = g_w2img + ((size_t)(layer*4 + ch)*2) * 1024;
            #pragma unroll
            for (int i = 0; i < 8; i++) sB[tid + i*256] = gB[tid + i*256];
        }
        __syncthreads();

        for (int kt = 0; kt < 4; kt++) {
            int ktg = ch*4 + kt;
            uint4 aH[2], aL[2];
            #pragma unroll
            for (int s = 0; s < 2; s++) {
                int idx = ((mw*2 + s)*16 + ktg)*32 + lane;
                aH[s] = hs4[idx];
                aL[s] = hs4[4096 + idx];
            }
            uint4 bH[4], bL[4];
            #pragma unroll
            for (int j = 0; j < 4; j++) {
                int idx = ((nw*4 + j)*4 + kt)*32 + lane;
                bH[j] = sB[idx];
                bL[j] = sB[1024 + idx];
            }
            #pragma unroll
            for (int j = 0; j < 4; j++)
                #pragma unroll
                for (int s = 0; s < 2; s++) {
                    mma16816(acc2[s][2*j],   aH[s], bH[j].x, bH[j].y);
                    mma16816(acc2[s][2*j+1], aH[s], bH[j].z, bH[j].w);
                    mma16816(acc2[s][2*j],   aH[s], bL[j].x, bL[j].y);
                    mma16816(acc2[s][2*j+1], aH[s], bL[j].z, bL[j].w);
                    mma16816(acc2[s][2*j],   aL[s], bH[j].x, bH[j].y);
                    mma16816(acc2[s][2*j+1], aL[s], bH[j].z, bH[j].w);
                }
        }
    }

    #pragma unroll
    for (int s = 0; s < 2; s++)
        #pragma unroll
        for (int nt = 0; nt < 8; nt++) {
            int R = mw*32 + s*16 + g;
            int C = nw*64 + nt*8 + tg*2;
            float2 v0 = make_float2(acc2[s][nt][0], acc2[s][nt][1]);
            float2 v1 = make_float2(acc2[s][nt][2], acc2[s][nt][3]);
            *(float2*)&g_m[(size_t)(e0 + R)*CCH + C]     = v0;
            *(float2*)&g_m[(size_t)(e0 + R + 8)*CCH + C] = v1;
        }
}

// ---------------- k_agg ----------------
__global__ void k_agg() {
    int n = blockIdx.x, tid = threadIdx.x;
    __shared__ float mS[NBR*CCH];
    __shared__ float yS[NBR*KH];
    int eb = n*NBR;
    for (int i = tid; i < NBR*CCH; i += 128) mS[i] = g_m[eb*CCH + i];
    for (int i = tid; i < NBR*KH;  i += 128) yS[i] = g_Y[eb*KH + i];
    __syncthreads();
    int c = tid;
    float acc[KH];
    #pragma unroll
    for (int k = 0; k < KH; k++) acc[k] = 0.f;
    #pragma unroll
    for (int e = 0; e < NBR; e++) {
        float mv = mS[e*CCH + c];
        #pragma unroll
        for (int k = 0; k < KH; k++) acc[k] = fmaf(yS[e*KH + k], mv, acc[k]);
    }
    #pragma unroll
    for (int k = 0; k < KH; k++) g_x[(n*KH + k)*CCH + c] += acc[k]*0.05f;
}

// ---------------- k_hw ----------------
__global__ void k_hw(const float* __restrict__ wf) {
    int n = blockIdx.x, lane = threadIdx.x;
    float v = 0.f;
    for (int c = lane; c < CCH; c += 32) v += g_x[n*(KH*CCH) + c]*wf[c];
    #pragma unroll
    for (int off = 16; off; off >>= 1) v += __shfl_xor_sync(0xffffffffu, v, off);
    if (lane == 0) g_hw[n] = v;
}

// ---------------- k_out ----------------
__global__ void k_out(const float* __restrict__ Wa, const float* __restrict__ ba,
                      const int* __restrict__ ei, float* __restrict__ out) {
    int n = blockIdx.x, tid = threadIdx.x;
    __shared__ float hs[CCH];
    hs[tid] = g_x[n*(KH*CCH) + tid];
    __syncthreads();
    if (tid < 100) {
        float acc = ba[tid];
        for (int c = 0; c < CCH; c++) acc = fmaf(hs[c], Wa[c*100 + tid], acc);
        out[NATOM*3 + n*100 + tid] = acc;
    } else if (tid < 103) {
        int j = tid - 100;
        float hwn = g_hw[n];
        float acc = 0.f;
        for (int e = 0; e < NBR; e++) {
            int ge = n*NBR + e;
            acc = fmaf(g_hw[ei[ge]] - hwn, g_dirn[ge*3 + j], acc);
        }
        out[n*3 + j] = acc;
    }
}

// ---------------- launch ----------------
static const int SMEM_S = (XS_F + YS_F)*4 + 640*4;   // 99840

extern "C" void kernel_launch(void* const* d_in, const int* in_sizes, int n_in,
                              void* d_out, int out_size) {
    const float* z       = (const float*)d_in[0];
    const float* frac    = (const float*)d_in[1];
    const int*   types   = (const int*)  d_in[2];
    const float* lengths = (const float*)d_in[4];
    const float* angles  = (const float*)d_in[5];
    const int*   batch   = (const int*)  d_in[6];
    const int*   ei      = (const int*)  d_in[7];
    const float* emb     = (const float*)d_in[8];
    const float* zproj   = (const float*)d_in[9];
    const float* Wd      = (const float*)d_in[10];
    const float* W1      = (const float*)d_in[11];
    const float* W2      = (const float*)d_in[12];
    const float* Wa      = (const float*)d_in[13];
    const float* ba      = (const float*)d_in[14];
    const float* wf      = (const float*)d_in[15];
    float* out = (float*)d_out;

    cudaFuncSetAttribute(k_s,   cudaFuncAttributeMaxDynamicSharedMemorySize, SMEM_S);
    cudaFuncSetAttribute(k_mlp, cudaFuncAttributeMaxDynamicSharedMemorySize, SM_MLP);

    k_wconv<<<384, 256>>>(W1, Wd, W2);
    k_prep <<<NCRYST, 128>>>(z, frac, lengths, angles, zproj);
    k_xinit<<<NATOM, 128>>>(types, batch, emb);
    k_edge <<<NEDGE/32, 128>>>(ei);
    k_aprep<<<2560, 256>>>();                 // rbf chunks, once
    for (int l = 0; l < NLAYER; l++) {
        k_s  <<<dim3(8, NCRYST), 256, SMEM_S>>>(ei);
        k_mlp<<<NCTA_MLP, 256, SM_MLP>>>(l);
        k_agg<<<NATOM, 128>>>();
    }
    k_hw <<<NATOM, 32>>>(wf);
    k_out<<<NATOM, 128>>>(Wa, ba, ei, out);
}

// round 7
// speedup vs baseline: 2.4057x; 1.1394x over previous
#include <cuda_runtime.h>
#include <cuda_bf16.h>
#include <math.h>
#include <stdint.h>

#define NCRYST 64
#define ATOMS  32
#define NATOM  2048
#define NBR    20
#define NEDGE  40960
#define CCH    128
#define HID    256
#define NBIN   128
#define NLAYER 8
#define KH     19
#define NCTA_MLP (NEDGE/128)     // 320

typedef unsigned long long u64;
typedef unsigned int u32;

// ---------------- scratch ----------------
__device__ float g_pos [NATOM * 3];
__device__ float g_dirn[NEDGE * 3];
__device__ float g_Y   [NEDGE * KH];
__device__ float g_rbf [NEDGE * NBIN];
__device__ float g_x   [NATOM * KH * CCH];
__device__ float g_s   [NEDGE * CCH];
__device__ float g_m   [NEDGE * CCH];
__device__ float g_zc  [NCRYST * CCH];
__device__ float g_hw  [NATOM];
__device__ uint4 g_w1img[8*2*4*2*1024];          // 2 MB
__device__ uint4 g_w2img[8*4*2*1024];            // 1 MB
__device__ uint4 g_aimg [NCTA_MLP*4*2*1024];     // rbf chunks 2,3 used

// ---------------- helpers ----------------
__device__ __forceinline__ u32 s2u(const void* p){ return (u32)__cvta_generic_to_shared(p); }
__device__ __forceinline__ void cpasync16(void* dst, const void* src){
    asm volatile("cp.async.cg.shared.global [%0], [%1], 16;" :: "r"(s2u(dst)), "l"(src));
}
#define CP_COMMIT asm volatile("cp.async.commit_group;" ::: "memory")
#define CP_WAIT0  asm volatile("cp.async.wait_group 0;" ::: "memory")

__device__ __forceinline__ void split2(float v0, float v1, u32& hi, u32& lo){
    __nv_bfloat16 h0 = __float2bfloat16_rn(v0);
    __nv_bfloat16 h1 = __float2bfloat16_rn(v1);
    float l0 = v0 - __bfloat162float(h0);
    float l1 = v1 - __bfloat162float(h1);
    __nv_bfloat162 H; H.x = h0; H.y = h1;
    __nv_bfloat162 L = __floats2bfloat162_rn(l0, l1);
    hi = *(u32*)&H; lo = *(u32*)&L;
}

__device__ __forceinline__ void mma16816(float* c, const uint4 a, const u32 b0, const u32 b1){
    asm volatile("mma.sync.aligned.m16n8k16.row.col.f32.bf16.bf16.f32 "
        "{%0,%1,%2,%3}, {%4,%5,%6,%7}, {%8,%9}, {%0,%1,%2,%3};"
        : "+f"(c[0]), "+f"(c[1]), "+f"(c[2]), "+f"(c[3])
        : "r"(a.x), "r"(a.y), "r"(a.z), "r"(a.w), "r"(b0), "r"(b1));
}

// ---------------- k_wconv ----------------
__global__ void k_wconv(const float* __restrict__ W1, const float* __restrict__ Wd,
                        const float* __restrict__ W2) {
    int t = blockIdx.x * 256 + threadIdx.x;
    if (t < 65536) {
        int l  = t >> 13;
        int r  = t & 8191;
        int nh = r >> 12;
        int ch = (r >> 10) & 3;
        int w  = r & 1023;
        int np = w >> 7, ktl = (w >> 5) & 3, lane = w & 31;
        int nE = nh*128 + np*16 + (lane >> 2);
        int nO = nE + 8;
        int k0 = ch*64 + ktl*16 + (lane & 3)*2;
        float v[8];
        #pragma unroll
        for (int q = 0; q < 4; q++) {
            int n = (q < 2) ? nE : nO;
            int kk = k0 + ((q & 1) ? 8 : 0);
            float a0, a1;
            if (kk < 128) { a0 = W1[l*32768 + kk*256 + n];       a1 = W1[l*32768 + (kk+1)*256 + n]; }
            else          { a0 = Wd[l*32768 + (kk-128)*256 + n]; a1 = Wd[l*32768 + (kk-127)*256 + n]; }
            v[q*2] = a0; v[q*2+1] = a1;
        }
        uint4 hi, lo;
        split2(v[0], v[1], hi.x, lo.x);
        split2(v[2], v[3], hi.y, lo.y);
        split2(v[4], v[5], hi.z, lo.z);
        split2(v[6], v[7], hi.w, lo.w);
        size_t base = ((size_t)((l*2 + nh)*4 + ch)*2) * 1024 + w;
        g_w1img[base]        = hi;
        g_w1img[base + 1024] = lo;
    } else if (t < 98304) {
        int u  = t - 65536;
        int l  = u >> 12;
        int ch = (u >> 10) & 3;
        int w  = u & 1023;
        int np = w >> 7, ktl = (w >> 5) & 3, lane = w & 31;
        int nE = np*16 + (lane >> 2);
        int nO = nE + 8;
        int k0 = ch*64 + ktl*16 + (lane & 3)*2;
        float v[8];
        #pragma unroll
        for (int q = 0; q < 4; q++) {
            int n = (q < 2) ? nE : nO;
            int kk = k0 + ((q & 1) ? 8 : 0);
            v[q*2]   = W2[l*32768 + kk*128 + n];
            v[q*2+1] = W2[l*32768 + (kk+1)*128 + n];
        }
        uint4 hi, lo;
        split2(v[0], v[1], hi.x, lo.x);
        split2(v[2], v[3], hi.y, lo.y);
        split2(v[4], v[5], hi.z, lo.z);
        split2(v[6], v[7], hi.w, lo.w);
        size_t base = ((size_t)(l*4 + ch)*2) * 1024 + w;
        g_w2img[base]        = hi;
        g_w2img[base + 1024] = lo;
    }
}

// ---------------- k_aprep: bake rbf fragment images (once) ----------------
__global__ void k_aprep() {
    int t = blockIdx.x * 256 + threadIdx.x;
    int cta = t >> 11;
    int r   = t & 2047;
    int chl = r >> 10;
    int w   = r & 1023;
    int mt = w >> 7, ktl = (w >> 5) & 3, lane = w & 31;
    int m0 = mt*16 + (lane >> 2);
    int kk = chl*64 + ktl*16 + (lane & 3)*2;
    size_t row0 = (size_t)(cta*128 + m0) * 128;
    size_t row1 = row0 + 8*128;
    float2 p00 = *(const float2*)&g_rbf[row0 + kk];
    float2 p10 = *(const float2*)&g_rbf[row1 + kk];
    float2 p01 = *(const float2*)&g_rbf[row0 + kk + 8];
    float2 p11 = *(const float2*)&g_rbf[row1 + kk + 8];
    uint4 hi, lo;
    split2(p00.x, p00.y, hi.x, lo.x);
    split2(p10.x, p10.y, hi.y, lo.y);
    split2(p01.x, p01.y, hi.z, lo.z);
    split2(p11.x, p11.y, hi.w, lo.w);
    int cg = chl + 2;
    size_t base = ((size_t)(cta*4 + cg)*2) * 1024 + w;
    g_aimg[base]        = hi;
    g_aimg[base + 1024] = lo;
}

// ---------------- k_prep ----------------
__global__ void k_prep(const float* __restrict__ z, const float* __restrict__ frac,
                       const float* __restrict__ lengths, const float* __restrict__ angles,
                       const float* __restrict__ zproj) {
    int cb = blockIdx.x, tid = threadIdx.x;
    __shared__ float lat[9];
    __shared__ float zs[256];
    if (tid == 0) {
        float a = lengths[cb*3+0], b = lengths[cb*3+1], c = lengths[cb*3+2];
        const float D2R = 0.017453292519943295f;
        float r0 = angles[cb*3+0]*D2R, r1 = angles[cb*3+1]*D2R, r2 = angles[cb*3+2]*D2R;
        float ca = cosf(r0), cbta = cosf(r1), cg = cosf(r2), sg = sinf(r2);
        float v3y = (ca - cbta*cg)/sg;
        float t = 1.0f - cbta*cbta - v3y*v3y;
        if (t < 1e-8f) t = 1e-8f;
        float v3z = sqrtf(t);
        lat[0]=a;        lat[1]=0.f;     lat[2]=0.f;
        lat[3]=b*cg;     lat[4]=b*sg;    lat[5]=0.f;
        lat[6]=c*cbta;   lat[7]=c*v3y;   lat[8]=c*v3z;
    }
    for (int i = tid; i < 256; i += blockDim.x) zs[i] = z[cb*256 + i];
    __syncthreads();
    if (tid < 96) {
        int a = tid/3, j = tid%3;
        int n = cb*ATOMS + a;
        g_pos[n*3+j] = frac[n*3+0]*lat[0+j] + frac[n*3+1]*lat[3+j] + frac[n*3+2]*lat[6+j];
    }
    float acc = 0.f;
    for (int i = 0; i < 256; i++) acc += zs[i]*zproj[i*CCH + tid];
    g_zc[cb*CCH + tid] = acc;
}

// ---------------- k_xinit ----------------
__global__ void k_xinit(const int* __restrict__ types, const int* __restrict__ batch,
                        const float* __restrict__ emb) {
    int n = blockIdx.x, c = threadIdx.x;
    int t = types[n];
    g_x[(n*KH + 0)*CCH + c] = emb[t*CCH + c] + g_zc[batch[n]*CCH + c];
    #pragma unroll
    for (int k = 1; k < KH; k++) g_x[(n*KH + k)*CCH + c] = 0.f;
}

// ---------------- k_edge ----------------
__global__ void k_edge(const int* __restrict__ ei) {
    int tid = threadIdx.x;
    int e0 = blockIdx.x * 32;
    __shared__ float ds[32];
    if (tid < 32) {
        int e = e0 + tid;
        int s = ei[e], d = ei[NEDGE + e];
        float vx = g_pos[s*3+0]-g_pos[d*3+0];
        float vy = g_pos[s*3+1]-g_pos[d*3+1];
        float vz = g_pos[s*3+2]-g_pos[d*3+2];
        float dist = sqrtf(vx*vx + vy*vy + vz*vz) + 1e-8f;
        ds[tid] = dist;
        float dx = vx/dist, dy = vy/dist, dz = vz/dist;
        g_dirn[e*3+0]=dx; g_dirn[e*3+1]=dy; g_dirn[e*3+2]=dz;
        float ct = dz;
        float rho = sqrtf(dx*dx + dy*dy) + 1e-12f;
        float cph = dx/rho, sph = dy/rho;
        float P0[7]; P0[0]=1.f; P0[1]=ct;
        #pragma unroll
        for (int l=2;l<=6;l++) P0[l] = ((2*l-1)*ct*P0[l-1] - (l-1)*P0[l-2]) / l;
        float P1[7]; P1[0]=0.f; P1[1]=-rho; P1[2]=-3.f*ct*rho;
        #pragma unroll
        for (int l=3;l<=6;l++) P1[l] = ((2*l-1)*ct*P1[l-1] - l*P1[l-2]) / (l-1);
        float* Yp = &g_Y[e*KH];
        const float FPI = 12.566370614359172f;
        Yp[0] = 0.28209479177387814f;
        int idx = 1;
        #pragma unroll
        for (int l=1;l<=6;l++) {
            float K0 = sqrtf((2*l+1)/FPI);
            float K1 = sqrtf(2.f*(2*l+1)/(FPI*l*(l+1)));
            Yp[idx++] = K1*P1[l]*sph;
            Yp[idx++] = K0*P0[l];
            Yp[idx++] = K1*P1[l]*cph;
        }
    }
    __syncthreads();
    const float step = 8.0f/127.0f;
    const float inv  = 127.0f/8.0f;
    for (int el = 0; el < 32; el++) {
        float d = ds[el];
        float t = (d - step*(float)tid)*inv;
        g_rbf[(e0+el)*NBIN + tid] = expf(-0.5f*t*t);
    }
}

// ---------------- k_s ----------------
#define XS_STRIDE 20
#define XS_F (ATOMS*KH*XS_STRIDE)
#define YS_F (640*KH)
__global__ __launch_bounds__(256, 2) void k_s(const int* __restrict__ ei) {
    int cq = blockIdx.x;
    int cb = blockIdx.y;
    int tid = threadIdx.x;
    extern __shared__ float sm[];
    float* xs  = sm;
    float* Ys  = sm + XS_F;
    int*  srcs = (int*)(Ys + YS_F);
    int abase = cb*ATOMS;
    int c0 = cq*16;
    for (int i = tid; i < ATOMS*KH*16; i += 256) {
        int a = i/(KH*16); int r = i - a*(KH*16); int k = r >> 4; int c = r & 15;
        xs[(a*KH + k)*XS_STRIDE + c] = g_x[((abase+a)*KH + k)*CCH + c0 + c];
    }
    int ebase = cb*640;
    for (int i = tid; i < YS_F; i += 256) Ys[i] = g_Y[ebase*KH + i];
    for (int i = tid; i < 640; i += 256) srcs[i] = ei[ebase + i] - abase;
    __syncthreads();
    int cg = tid & 3, er = tid >> 2;
    #pragma unroll 2
    for (int j = 0; j < 10; j++) {
        int e = j*64 + er;
        int sl = srcs[e];
        const float* xr = &xs[sl*(KH*XS_STRIDE) + cg*4];
        const float* yr = &Ys[e*KH];
        float4 acc = make_float4(0.f, 0.f, 0.f, 0.f);
        #pragma unroll
        for (int k = 0; k < KH; k++) {
            float y = yr[k];
            float4 xv = *(const float4*)&xr[k*XS_STRIDE];
            acc.x = fmaf(y, xv.x, acc.x);
            acc.y = fmaf(y, xv.y, acc.y);
            acc.z = fmaf(y, xv.z, acc.z);
            acc.w = fmaf(y, xv.w, acc.w);
        }
        *(float4*)&g_s[(size_t)(ebase+e)*CCH + c0 + cg*4] = acc;
    }
}

// ---------------- k_mlp: pipelined mma.sync bf16 3-pass ----------------
// smem map (192 KB):
//   GEMM1 mainloop: Bping[2] @ 0 / 65536 (64KB each: [nh][img][1024 u4]); sA @ 131072 (32KB)
//   after GEMM1:    hs (h fragments) @ 0..131072 ; GEMM2 B ping @ 131072 / 163840 (32KB each)
#define SM_MLP   196608

__global__ __launch_bounds__(256, 1) void k_mlp(int layer) {
    extern __shared__ char smem[];
    int tid = threadIdx.x;
    int wid = tid >> 5, lane = tid & 31;
    int mw = wid & 3, nw = wid >> 2;
    int cta = blockIdx.x;
    int e0 = cta * 128;
    int g  = lane >> 2;
    int tg = lane & 3;

    uint4* Bb0 = (uint4*)smem;
    uint4* Bb1 = (uint4*)(smem + 65536);
    uint4* sA  = (uint4*)(smem + 131072);
    uint4* hs4 = (uint4*)smem;
    u32*   hsw = (u32*)smem;

    // ---- prefetch B1(ch=0), both nhalfs ----
    {
        const uint4* g0 = g_w1img + ((size_t)((layer*2 + 0)*4 + 0)*2) * 1024;
        const uint4* g1 = g_w1img + ((size_t)((layer*2 + 1)*4 + 0)*2) * 1024;
        #pragma unroll
        for (int i = 0; i < 8; i++) cpasync16(&Bb0[tid + i*256],        &g0[tid + i*256]);
        #pragma unroll
        for (int i = 0; i < 8; i++) cpasync16(&Bb0[2048 + tid + i*256], &g1[tid + i*256]);
        CP_COMMIT;
    }

    float acc1[2][2][8][4];
    #pragma unroll
    for (int nh = 0; nh < 2; nh++)
        #pragma unroll
        for (int s = 0; s < 2; s++)
            #pragma unroll
            for (int j = 0; j < 8; j++)
                #pragma unroll
                for (int q = 0; q < 4; q++) acc1[nh][s][j][q] = 0.f;

    // ===================== GEMM1 mainloop =====================
    for (int ch = 0; ch < 4; ch++) {
        __syncthreads();   // prior compute done (sA / B reuse safe)
        if (ch < 2) {
            // build s-chunk A-fragments from g_s (plain stores)
            #pragma unroll
            for (int i = 0; i < 4; i++) {
                int w = tid + i*256;
                int mt = w >> 7, ktl = (w >> 5) & 3, ln = w & 31;
                int m0 = mt*16 + (ln >> 2);
                int kk = ch*64 + ktl*16 + (ln & 3)*2;
                size_t row0 = (size_t)(e0 + m0)*CCH;
                size_t row1 = row0 + 8*CCH;
                float2 p00 = *(const float2*)&g_s[row0 + kk];
                float2 p10 = *(const float2*)&g_s[row1 + kk];
                float2 p01 = *(const float2*)&g_s[row0 + kk + 8];
                float2 p11 = *(const float2*)&g_s[row1 + kk + 8];
                uint4 hi, lo;
                split2(p00.x, p00.y, hi.x, lo.x);
                split2(p10.x, p10.y, hi.y, lo.y);
                split2(p01.x, p01.y, hi.z, lo.z);
                split2(p11.x, p11.y, hi.w, lo.w);
                sA[w]        = hi;
                sA[1024 + w] = lo;
            }
        } else {
            const uint4* gA = g_aimg + ((size_t)(cta*4 + ch)*2) * 1024;
            #pragma unroll
            for (int i = 0; i < 8; i++) cpasync16(&sA[tid + i*256], &gA[tid + i*256]);
        }
        CP_COMMIT;
        CP_WAIT0;            // B(ch) [+ async A(ch)] landed
        __syncthreads();
        uint4* Bcur = (ch & 1) ? Bb1 : Bb0;
        if (ch < 3) {        // prefetch next B into other buffer
            uint4* Bnx = (ch & 1) ? Bb0 : Bb1;
            const uint4* g0 = g_w1img + ((size_t)((layer*2 + 0)*4 + (ch+1))*2) * 1024;
            const uint4* g1 = g_w1img + ((size_t)((layer*2 + 1)*4 + (ch+1))*2) * 1024;
            #pragma unroll
            for (int i = 0; i < 8; i++) cpasync16(&Bnx[tid + i*256],        &g0[tid + i*256]);
            #pragma unroll
            for (int i = 0; i < 8; i++) cpasync16(&Bnx[2048 + tid + i*256], &g1[tid + i*256]);
            CP_COMMIT;
        }
        // compute: both nhalfs
        #pragma unroll
        for (int kt = 0; kt < 4; kt++) {
            uint4 aH[2], aL[2];
            #pragma unroll
            for (int s = 0; s < 2; s++) {
                int idx = ((mw*2 + s)*4 + kt)*32 + lane;
                aH[s] = sA[idx];
                aL[s] = sA[1024 + idx];
            }
            #pragma unroll
            for (int nh = 0; nh < 2; nh++) {
                const uint4* Bv = Bcur + nh*2048;
                uint4 bH[4], bL[4];
                #pragma unroll
                for (int j = 0; j < 4; j++) {
                    int idx = ((nw*4 + j)*4 + kt)*32 + lane;
                    bH[j] = Bv[idx];
                    bL[j] = Bv[1024 + idx];
                }
                #pragma unroll
                for (int j = 0; j < 4; j++)
                    #pragma unroll
                    for (int s = 0; s < 2; s++) {
                        mma16816(acc1[nh][s][2*j],   aH[s], bH[j].x, bH[j].y);
                        mma16816(acc1[nh][s][2*j+1], aH[s], bH[j].z, bH[j].w);
                        mma16816(acc1[nh][s][2*j],   aH[s], bL[j].x, bL[j].y);
                        mma16816(acc1[nh][s][2*j+1], aH[s], bL[j].z, bL[j].w);
                        mma16816(acc1[nh][s][2*j],   aL[s], bH[j].x, bH[j].y);
                        mma16816(acc1[nh][s][2*j+1], aL[s], bH[j].z, bH[j].w);
                    }
            }
        }
    }
    __syncthreads();   // all B/A reads done; hs region free

    // prefetch GEMM2 B(0) into sA region (dead) while epilogue runs
    {
        const uint4* gB = g_w2img + ((size_t)(layer*4 + 0)*2) * 1024;
        #pragma unroll
        for (int i = 0; i < 8; i++) cpasync16(&sA[tid + i*256], &gB[tid + i*256]);
        CP_COMMIT;
    }

    // ---- epilogue 1: silu + split -> h fragments (GEMM2 A layout) ----
    #pragma unroll
    for (int nh = 0; nh < 2; nh++)
        #pragma unroll
        for (int s = 0; s < 2; s++)
            #pragma unroll
            for (int nt = 0; nt < 8; nt++) {
                float c0 = acc1[nh][s][nt][0], c1 = acc1[nh][s][nt][1];
                float c2 = acc1[nh][s][nt][2], c3 = acc1[nh][s][nt][3];
                c0 = c0 / (1.f + __expf(-c0));
                c1 = c1 / (1.f + __expf(-c1));
                c2 = c2 / (1.f + __expf(-c2));
                c3 = c3 / (1.f + __expf(-c3));
                int R = mw*32 + s*16 + g;
                int C = nh*128 + nw*64 + nt*8 + tg*2;
                u32 hi01, lo01, hi23, lo23;
                split2(c0, c1, hi01, lo01);
                split2(c2, c3, hi23, lo23);
                int mtp  = R >> 4;
                int ktp  = C >> 4;
                int khal = (C >> 3) & 1;
                int lanep = g*4 + tg;
                u32 base = (((u32)(mtp*16 + ktp)*32 + lanep) << 2);
                hsw[base + 2*khal]             = hi01;
                hsw[base + 2*khal + 1]         = hi23;
                hsw[16384 + base + 2*khal]     = lo01;
                hsw[16384 + base + 2*khal + 1] = lo23;
            }
    CP_WAIT0;
    __syncthreads();

    // ===================== GEMM2 =====================
    float acc2[2][8][4];
    #pragma unroll
    for (int i = 0; i < 2; i++)
        #pragma unroll
        for (int j = 0; j < 8; j++)
            #pragma unroll
            for (int q = 0; q < 4; q++) acc2[i][j][q] = 0.f;

    uint4* B2[2] = { (uint4*)(smem + 131072), (uint4*)(smem + 163840) };
    for (int ch = 0; ch < 4; ch++) {
        if (ch < 3) {
            const uint4* gB = g_w2img + ((size_t)(layer*4 + ch + 1)*2) * 1024;
            uint4* Bnx = B2[(ch+1) & 1];
            #pragma unroll
            for (int i = 0; i < 8; i++) cpasync16(&Bnx[tid + i*256], &gB[tid + i*256]);
            CP_COMMIT;
        }
        const uint4* Bcur = B2[ch & 1];
        #pragma unroll
        for (int kt = 0; kt < 4; kt++) {
            int ktg = ch*4 + kt;
            uint4 aH[2], aL[2];
            #pragma unroll
            for (int s = 0; s < 2; s++) {
                int idx = ((mw*2 + s)*16 + ktg)*32 + lane;
                aH[s] = hs4[idx];
                aL[s] = hs4[4096 + idx];
            }
            uint4 bH[4], bL[4];
            #pragma unroll
            for (int j = 0; j < 4; j++) {
                int idx = ((nw*4 + j)*4 + kt)*32 + lane;
                bH[j] = Bcur[idx];
                bL[j] = Bcur[1024 + idx];
            }
            #pragma unroll
            for (int j = 0; j < 4; j++)
                #pragma unroll
                for (int s = 0; s < 2; s++) {
                    mma16816(acc2[s][2*j],   aH[s], bH[j].x, bH[j].y);
                    mma16816(acc2[s][2*j+1], aH[s], bH[j].z, bH[j].w);
                    mma16816(acc2[s][2*j],   aH[s], bL[j].x, bL[j].y);
                    mma16816(acc2[s][2*j+1], aH[s], bL[j].z, bL[j].w);
                    mma16816(acc2[s][2*j],   aL[s], bH[j].x, bH[j].y);
                    mma16816(acc2[s][2*j+1], aL[s], bH[j].z, bH[j].w);
                }
        }
        if (ch < 3) { CP_WAIT0; __syncthreads(); }
    }

    #pragma unroll
    for (int s = 0; s < 2; s++)
        #pragma unroll
        for (int nt = 0; nt < 8; nt++) {
            int R = mw*32 + s*16 + g;
            int C = nw*64 + nt*8 + tg*2;
            float2 v0 = make_float2(acc2[s][nt][0], acc2[s][nt][1]);
            float2 v1 = make_float2(acc2[s][nt][2], acc2[s][nt][3]);
            *(float2*)&g_m[(size_t)(e0 + R)*CCH + C]     = v0;
            *(float2*)&g_m[(size_t)(e0 + R + 8)*CCH + C] = v1;
        }
}

// ---------------- k_agg ----------------
__global__ void k_agg() {
    int n = blockIdx.x, tid = threadIdx.x;
    __shared__ float mS[NBR*CCH];
    __shared__ float yS[NBR*KH];
    int eb = n*NBR;
    for (int i = tid; i < NBR*CCH; i += 128) mS[i] = g_m[eb*CCH + i];
    for (int i = tid; i < NBR*KH;  i += 128) yS[i] = g_Y[eb*KH + i];
    __syncthreads();
    int c = tid;
    float acc[KH];
    #pragma unroll
    for (int k = 0; k < KH; k++) acc[k] = 0.f;
    #pragma unroll
    for (int e = 0; e < NBR; e++) {
        float mv = mS[e*CCH + c];
        #pragma unroll
        for (int k = 0; k < KH; k++) acc[k] = fmaf(yS[e*KH + k], mv, acc[k]);
    }
    #pragma unroll
    for (int k = 0; k < KH; k++) g_x[(n*KH + k)*CCH + c] += acc[k]*0.05f;
}

// ---------------- k_hw ----------------
__global__ void k_hw(const float* __restrict__ wf) {
    int n = blockIdx.x, lane = threadIdx.x;
    float v = 0.f;
    for (int c = lane; c < CCH; c += 32) v += g_x[n*(KH*CCH) + c]*wf[c];
    #pragma unroll
    for (int off = 16; off; off >>= 1) v += __shfl_xor_sync(0xffffffffu, v, off);
    if (lane == 0) g_hw[n] = v;
}

// ---------------- k_out ----------------
__global__ void k_out(const float* __restrict__ Wa, const float* __restrict__ ba,
                      const int* __restrict__ ei, float* __restrict__ out) {
    int n = blockIdx.x, tid = threadIdx.x;
    __shared__ float hs[CCH];
    hs[tid] = g_x[n*(KH*CCH) + tid];
    __syncthreads();
    if (tid < 100) {
        float acc = ba[tid];
        for (int c = 0; c < CCH; c++) acc = fmaf(hs[c], Wa[c*100 + tid], acc);
        out[NATOM*3 + n*100 + tid] = acc;
    } else if (tid < 103) {
        int j = tid - 100;
        float hwn = g_hw[n];
        float acc = 0.f;
        for (int e = 0; e < NBR; e++) {
            int ge = n*NBR + e;
            acc = fmaf(g_hw[ei[ge]] - hwn, g_dirn[ge*3 + j], acc);
        }
        out[n*3 + j] = acc;
    }
}

// ---------------- launch ----------------
static const int SMEM_S = (XS_F + YS_F)*4 + 640*4;

extern "C" void kernel_launch(void* const* d_in, const int* in_sizes, int n_in,
                              void* d_out, int out_size) {
    const float* z       = (const float*)d_in[0];
    const float* frac    = (const float*)d_in[1];
    const int*   types   = (const int*)  d_in[2];
    const float* lengths = (const float*)d_in[4];
    const float* angles  = (const float*)d_in[5];
    const int*   batch   = (const int*)  d_in[6];
    const int*   ei      = (const int*)  d_in[7];
    const float* emb     = (const float*)d_in[8];
    const float* zproj   = (const float*)d_in[9];
    const float* Wd      = (const float*)d_in[10];
    const float* W1      = (const float*)d_in[11];
    const float* W2      = (const float*)d_in[12];
    const float* Wa      = (const float*)d_in[13];
    const float* ba      = (const float*)d_in[14];
    const float* wf      = (const float*)d_in[15];
    float* out = (float*)d_out;

    cudaFuncSetAttribute(k_s,   cudaFuncAttributeMaxDynamicSharedMemorySize, SMEM_S);
    cudaFuncSetAttribute(k_mlp, cudaFuncAttributeMaxDynamicSharedMemorySize, SM_MLP);

    k_wconv<<<384, 256>>>(W1, Wd, W2);
    k_prep <<<NCRYST, 128>>>(z, frac, lengths, angles, zproj);
    k_xinit<<<NATOM, 128>>>(types, batch, emb);
    k_edge <<<NEDGE/32, 128>>>(ei);
    k_aprep<<<2560, 256>>>();
    for (int l = 0; l < NLAYER; l++) {
        k_s  <<<dim3(8, NCRYST), 256, SMEM_S>>>(ei);
        k_mlp<<<NCTA_MLP, 256, SM_MLP>>>(l);
        k_agg<<<NATOM, 128>>>();
    }
    k_hw <<<NATOM, 32>>>(wf);
    k_out<<<NATOM, 128>>>(Wa, ba, ei, out);
}

// round 9
// speedup vs baseline: 2.7025x; 1.1234x over previous
#include <cuda_runtime.h>
#include <cuda_bf16.h>
#include <math.h>
#include <stdint.h>

#define NCRYST 64
#define ATOMS  32
#define NATOM  2048
#define NBR    20
#define NEDGE  40960
#define CCH    128
#define HID    256
#define NBIN   128
#define NLAYER 8
#define KH     19
#define NCTA_MLP (NEDGE/128)     // 320

typedef unsigned long long u64;
typedef unsigned int u32;

// ---------------- scratch ----------------
__device__ float g_dirn[NEDGE * 3];
__device__ float g_Y   [NEDGE * KH];
__device__ float g_rbf [NEDGE * NBIN];
__device__ float g_x   [NATOM * KH * CCH];
__device__ float g_s   [NEDGE * CCH];
__device__ float g_m   [NEDGE * CCH];
__device__ float g_hw  [NATOM];
__device__ uint4 g_w1img[8*2*4*2*1024];          // 2 MB
__device__ uint4 g_w2img[8*4*2*1024];            // 1 MB
__device__ uint4 g_aimg [NCTA_MLP*4*2*1024];     // rbf chunks 2,3 used

// ---------------- helpers ----------------
__device__ __forceinline__ u32 s2u(const void* p){ return (u32)__cvta_generic_to_shared(p); }
__device__ __forceinline__ void cpasync16(void* dst, const void* src){
    asm volatile("cp.async.cg.shared.global [%0], [%1], 16;" :: "r"(s2u(dst)), "l"(src));
}
#define CP_COMMIT asm volatile("cp.async.commit_group;" ::: "memory")
#define CP_WAIT0  asm volatile("cp.async.wait_group 0;" ::: "memory")

__device__ __forceinline__ void split2(float v0, float v1, u32& hi, u32& lo){
    __nv_bfloat16 h0 = __float2bfloat16_rn(v0);
    __nv_bfloat16 h1 = __float2bfloat16_rn(v1);
    float l0 = v0 - __bfloat162float(h0);
    float l1 = v1 - __bfloat162float(h1);
    __nv_bfloat162 H; H.x = h0; H.y = h1;
    __nv_bfloat162 L = __floats2bfloat162_rn(l0, l1);
    hi = *(u32*)&H; lo = *(u32*)&L;
}

__device__ __forceinline__ void mma16816(float* c, const uint4 a, const u32 b0, const u32 b1){
    asm volatile("mma.sync.aligned.m16n8k16.row.col.f32.bf16.bf16.f32 "
        "{%0,%1,%2,%3}, {%4,%5,%6,%7}, {%8,%9}, {%0,%1,%2,%3};"
        : "+f"(c[0]), "+f"(c[1]), "+f"(c[2]), "+f"(c[3])
        : "r"(a.x), "r"(a.y), "r"(a.z), "r"(a.w), "r"(b0), "r"(b1));
}

// ---------------- k_init: lattice, pos, zc, x-init, edges (dirn/Y/rbf), rbf-frag bake ----------------
__global__ __launch_bounds__(512) void k_init(
        const float* __restrict__ z, const float* __restrict__ frac,
        const float* __restrict__ lengths, const float* __restrict__ angles,
        const float* __restrict__ zproj, const int* __restrict__ types,
        const float* __restrict__ emb, const int* __restrict__ ei) {
    int cb = blockIdx.x, tid = threadIdx.x;
    __shared__ float lats[9];
    __shared__ float zs[256];
    __shared__ float poss[ATOMS*3];
    __shared__ float zcs[CCH];
    __shared__ float ds[640];
    int abase = cb*ATOMS;
    int ebase = cb*640;

    if (tid == 0) {
        float a = lengths[cb*3+0], b = lengths[cb*3+1], c = lengths[cb*3+2];
        const float D2R = 0.017453292519943295f;
        float r0 = angles[cb*3+0]*D2R, r1 = angles[cb*3+1]*D2R, r2 = angles[cb*3+2]*D2R;
        float ca = cosf(r0), cbta = cosf(r1), cg = cosf(r2), sg = sinf(r2);
        float v3y = (ca - cbta*cg)/sg;
        float t = 1.0f - cbta*cbta - v3y*v3y;
        if (t < 1e-8f) t = 1e-8f;
        float v3z = sqrtf(t);
        lats[0]=a;        lats[1]=0.f;     lats[2]=0.f;
        lats[3]=b*cg;     lats[4]=b*sg;    lats[5]=0.f;
        lats[6]=c*cbta;   lats[7]=c*v3y;   lats[8]=c*v3z;
    }
    if (tid < 256) zs[tid] = z[cb*256 + tid];
    __syncthreads();
    if (tid < 96) {
        int a = tid/3, j = tid%3;
        int n = abase + a;
        poss[a*3+j] = frac[n*3+0]*lats[0+j] + frac[n*3+1]*lats[3+j] + frac[n*3+2]*lats[6+j];
    }
    if (tid < 128) {
        float acc = 0.f;
        for (int i = 0; i < 256; i++) acc += zs[i]*zproj[i*CCH + tid];
        zcs[tid] = acc;
    }
    __syncthreads();

    // x init: x[:,0,:] = emb[type] + zc ; rest zero
    for (int i = tid; i < ATOMS*CCH; i += 512) {
        int a = i >> 7, c = i & 127;
        int n = abase + a;
        g_x[(size_t)(n*KH)*CCH + c] = emb[types[n]*CCH + c] + zcs[c];
    }
    for (int i4 = tid; i4 < ATOMS*18*CCH/4; i4 += 512) {
        int flat = i4*4;
        int a = flat/(18*CCH);
        int r = flat - a*(18*CCH);
        int k = 1 + (r >> 7), c = r & 127;
        *(float4*)&g_x[((size_t)(abase+a)*KH + k)*CCH + c] = make_float4(0.f,0.f,0.f,0.f);
    }

    // edges: dirn, Y
    for (int e = tid; e < 640; e += 512) {
        int s = ei[ebase + e] - abase, d = ei[NEDGE + ebase + e] - abase;
        float vx = poss[s*3+0]-poss[d*3+0];
        float vy = poss[s*3+1]-poss[d*3+1];
        float vz = poss[s*3+2]-poss[d*3+2];
        float dist = sqrtf(vx*vx + vy*vy + vz*vz) + 1e-8f;
        ds[e] = dist;
        float dx = vx/dist, dy = vy/dist, dz = vz/dist;
        int ge = ebase + e;
        g_dirn[ge*3+0]=dx; g_dirn[ge*3+1]=dy; g_dirn[ge*3+2]=dz;
        float ct = dz;
        float rho = sqrtf(dx*dx + dy*dy) + 1e-12f;
        float cph = dx/rho, sph = dy/rho;
        float P0[7]; P0[0]=1.f; P0[1]=ct;
        #pragma unroll
        for (int l=2;l<=6;l++) P0[l] = ((2*l-1)*ct*P0[l-1] - (l-1)*P0[l-2]) / l;
        float P1[7]; P1[0]=0.f; P1[1]=-rho; P1[2]=-3.f*ct*rho;
        #pragma unroll
        for (int l=3;l<=6;l++) P1[l] = ((2*l-1)*ct*P1[l-1] - l*P1[l-2]) / (l-1);
        float* Yp = &g_Y[(size_t)ge*KH];
        const float FPI = 12.566370614359172f;
        Yp[0] = 0.28209479177387814f;
        int idx = 1;
        #pragma unroll
        for (int l=1;l<=6;l++) {
            float K0 = sqrtf((2*l+1)/FPI);
            float K1 = sqrtf(2.f*(2*l+1)/(FPI*l*(l+1)));
            Yp[idx++] = K1*P1[l]*sph;
            Yp[idx++] = K0*P0[l];
            Yp[idx++] = K1*P1[l]*cph;
        }
    }
    __syncthreads();

    // rbf
    const float step = 8.0f/127.0f;
    const float inv  = 127.0f/8.0f;
    for (int i = tid; i < 640*NBIN; i += 512) {
        int e = i >> 7, bin = i & 127;
        float t = (ds[e] - step*(float)bin)*inv;
        g_rbf[(size_t)(ebase+e)*NBIN + bin] = expf(-0.5f*t*t);
    }
    __syncthreads();

    // bake rbf fragment images for this crystal's 5 mlp-CTAs (chunks 2,3)
    for (int i = tid; i < 5*2*1024; i += 512) {
        int lc  = i >> 11;
        int r   = i & 2047;
        int chl = r >> 10;
        int w   = r & 1023;
        int cta = cb*5 + lc;
        int mt = w >> 7, ktl = (w >> 5) & 3, lane = w & 31;
        int m0 = mt*16 + (lane >> 2);
        int kk = chl*64 + ktl*16 + (lane & 3)*2;
        size_t row0 = (size_t)(cta*128 + m0) * NBIN;
        size_t row1 = row0 + 8*NBIN;
        float2 p00 = *(const float2*)&g_rbf[row0 + kk];
        float2 p10 = *(const float2*)&g_rbf[row1 + kk];
        float2 p01 = *(const float2*)&g_rbf[row0 + kk + 8];
        float2 p11 = *(const float2*)&g_rbf[row1 + kk + 8];
        uint4 hi, lo;
        split2(p00.x, p00.y, hi.x, lo.x);
        split2(p10.x, p10.y, hi.y, lo.y);
        split2(p01.x, p01.y, hi.z, lo.z);
        split2(p11.x, p11.y, hi.w, lo.w);
        size_t base = ((size_t)(cta*4 + chl + 2)*2) * 1024 + w;
        g_aimg[base]        = hi;
        g_aimg[base + 1024] = lo;
    }
}

// ---------------- k_wconv ----------------
__global__ void k_wconv(const float* __restrict__ W1, const float* __restrict__ Wd,
                        const float* __restrict__ W2) {
    int t = blockIdx.x * 256 + threadIdx.x;
    if (t < 65536) {
        int l  = t >> 13;
        int r  = t & 8191;
        int nh = r >> 12;
        int ch = (r >> 10) & 3;
        int w  = r & 1023;
        int np = w >> 7, ktl = (w >> 5) & 3, lane = w & 31;
        int nE = nh*128 + np*16 + (lane >> 2);
        int nO = nE + 8;
        int k0 = ch*64 + ktl*16 + (lane & 3)*2;
        float v[8];
        #pragma unroll
        for (int q = 0; q < 4; q++) {
            int n = (q < 2) ? nE : nO;
            int kk = k0 + ((q & 1) ? 8 : 0);
            float a0, a1;
            if (kk < 128) { a0 = W1[l*32768 + kk*256 + n];       a1 = W1[l*32768 + (kk+1)*256 + n]; }
            else          { a0 = Wd[l*32768 + (kk-128)*256 + n]; a1 = Wd[l*32768 + (kk-127)*256 + n]; }
            v[q*2] = a0; v[q*2+1] = a1;
        }
        uint4 hi, lo;
        split2(v[0], v[1], hi.x, lo.x);
        split2(v[2], v[3], hi.y, lo.y);
        split2(v[4], v[5], hi.z, lo.z);
        split2(v[6], v[7], hi.w, lo.w);
        size_t base = ((size_t)((l*2 + nh)*4 + ch)*2) * 1024 + w;
        g_w1img[base]        = hi;
        g_w1img[base + 1024] = lo;
    } else if (t < 98304) {
        int u  = t - 65536;
        int l  = u >> 12;
        int ch = (u >> 10) & 3;
        int w  = u & 1023;
        int np = w >> 7, ktl = (w >> 5) & 3, lane = w & 31;
        int nE = np*16 + (lane >> 2);
        int nO = nE + 8;
        int k0 = ch*64 + ktl*16 + (lane & 3)*2;
        float v[8];
        #pragma unroll
        for (int q = 0; q < 4; q++) {
            int n = (q < 2) ? nE : nO;
            int kk = k0 + ((q & 1) ? 8 : 0);
            v[q*2]   = W2[l*32768 + kk*128 + n];
            v[q*2+1] = W2[l*32768 + (kk+1)*128 + n];
        }
        uint4 hi, lo;
        split2(v[0], v[1], hi.x, lo.x);
        split2(v[2], v[3], hi.y, lo.y);
        split2(v[4], v[5], hi.z, lo.z);
        split2(v[6], v[7], hi.w, lo.w);
        size_t base = ((size_t)(l*4 + ch)*2) * 1024 + w;
        g_w2img[base]        = hi;
        g_w2img[base + 1024] = lo;
    }
}

// ---------------- k_s ----------------
#define XS_STRIDE 20
#define XS_F (ATOMS*KH*XS_STRIDE)
#define YS_F (640*KH)
__global__ __launch_bounds__(256, 2) void k_s(const int* __restrict__ ei) {
    int cq = blockIdx.x;
    int cb = blockIdx.y;
    int tid = threadIdx.x;
    extern __shared__ float sm[];
    float* xs  = sm;
    float* Ys  = sm + XS_F;
    int*  srcs = (int*)(Ys + YS_F);
    int abase = cb*ATOMS;
    int c0 = cq*16;
    for (int i = tid; i < ATOMS*KH*16; i += 256) {
        int a = i/(KH*16); int r = i - a*(KH*16); int k = r >> 4; int c = r & 15;
        xs[(a*KH + k)*XS_STRIDE + c] = g_x[((size_t)(abase+a)*KH + k)*CCH + c0 + c];
    }
    int ebase = cb*640;
    for (int i = tid; i < YS_F; i += 256) Ys[i] = g_Y[(size_t)ebase*KH + i];
    for (int i = tid; i < 640; i += 256) srcs[i] = ei[ebase + i] - abase;
    __syncthreads();
    int cg = tid & 3, er = tid >> 2;
    #pragma unroll 2
    for (int j = 0; j < 10; j++) {
        int e = j*64 + er;
        int sl = srcs[e];
        const float* xr = &xs[sl*(KH*XS_STRIDE) + cg*4];
        const float* yr = &Ys[e*KH];
        float4 acc = make_float4(0.f, 0.f, 0.f, 0.f);
        #pragma unroll
        for (int k = 0; k < KH; k++) {
            float y = yr[k];
            float4 xv = *(const float4*)&xr[k*XS_STRIDE];
            acc.x = fmaf(y, xv.x, acc.x);
            acc.y = fmaf(y, xv.y, acc.y);
            acc.z = fmaf(y, xv.z, acc.z);
            acc.w = fmaf(y, xv.w, acc.w);
        }
        *(float4*)&g_s[(size_t)(ebase+e)*CCH + c0 + cg*4] = acc;
    }
}

// ---------------- k_mlp: 512 threads, 16 warps (4m x 4n), pipelined bf16 3-pass ----------------
#define SM_MLP   196608

__global__ __launch_bounds__(512, 1) void k_mlp(int layer) {
    extern __shared__ char smem[];
    int tid = threadIdx.x;
    int wid = tid >> 5, lane = tid & 31;
    int mw = wid & 3, nw = wid >> 2;       // 4 x 4
    int cta = blockIdx.x;
    int e0 = cta * 128;
    int g  = lane >> 2;
    int tg = lane & 3;

    uint4* Bb0 = (uint4*)smem;             // 64 KB: [nh][img][1024]
    uint4* Bb1 = (uint4*)(smem + 65536);
    uint4* sA  = (uint4*)(smem + 131072);  // 32 KB
    uint4* hs4 = (uint4*)smem;             // h frags after GEMM1
    u32*   hsw = (u32*)smem;

    int nh     = nw >> 1;
    int npbase = (nw & 1) * 4;

    // prefetch B1(ch=0), both nhalfs
    {
        const uint4* g0 = g_w1img + ((size_t)((layer*2 + 0)*4 + 0)*2) * 1024;
        const uint4* g1 = g_w1img + ((size_t)((layer*2 + 1)*4 + 0)*2) * 1024;
        #pragma unroll
        for (int i = 0; i < 4; i++) cpasync16(&Bb0[tid + i*512],        &g0[tid + i*512]);
        #pragma unroll
        for (int i = 0; i < 4; i++) cpasync16(&Bb0[2048 + tid + i*512], &g1[tid + i*512]);
        CP_COMMIT;
    }

    float acc1[2][8][4];
    #pragma unroll
    for (int s = 0; s < 2; s++)
        #pragma unroll
        for (int j = 0; j < 8; j++)
            #pragma unroll
            for (int q = 0; q < 4; q++) acc1[s][j][q] = 0.f;

    // ===================== GEMM1 =====================
    for (int ch = 0; ch < 4; ch++) {
        __syncthreads();
        if (ch < 2) {
            #pragma unroll
            for (int w = tid; w < 1024; w += 512) {
                int mt = w >> 7, ktl = (w >> 5) & 3, ln = w & 31;
                int m0 = mt*16 + (ln >> 2);
                int kk = ch*64 + ktl*16 + (ln & 3)*2;
                size_t row0 = (size_t)(e0 + m0)*CCH;
                size_t row1 = row0 + 8*CCH;
                float2 p00 = *(const float2*)&g_s[row0 + kk];
                float2 p10 = *(const float2*)&g_s[row1 + kk];
                float2 p01 = *(const float2*)&g_s[row0 + kk + 8];
                float2 p11 = *(const float2*)&g_s[row1 + kk + 8];
                uint4 hi, lo;
                split2(p00.x, p00.y, hi.x, lo.x);
                split2(p10.x, p10.y, hi.y, lo.y);
                split2(p01.x, p01.y, hi.z, lo.z);
                split2(p11.x, p11.y, hi.w, lo.w);
                sA[w]        = hi;
                sA[1024 + w] = lo;
            }
        } else {
            const uint4* gA = g_aimg + ((size_t)(cta*4 + ch)*2) * 1024;
            #pragma unroll
            for (int i = 0; i < 4; i++) cpasync16(&sA[tid + i*512], &gA[tid + i*512]);
        }
        CP_COMMIT;
        CP_WAIT0;
        __syncthreads();
        uint4* Bcur = (ch & 1) ? Bb1 : Bb0;
        if (ch < 3) {
            uint4* Bnx = (ch & 1) ? Bb0 : Bb1;
            const uint4* g0 = g_w1img + ((size_t)((layer*2 + 0)*4 + (ch+1))*2) * 1024;
            const uint4* g1 = g_w1img + ((size_t)((layer*2 + 1)*4 + (ch+1))*2) * 1024;
            #pragma unroll
            for (int i = 0; i < 4; i++) cpasync16(&Bnx[tid + i*512],        &g0[tid + i*512]);
            #pragma unroll
            for (int i = 0; i < 4; i++) cpasync16(&Bnx[2048 + tid + i*512], &g1[tid + i*512]);
            CP_COMMIT;
        }
        #pragma unroll
        for (int kt = 0; kt < 4; kt++) {
            uint4 aH[2], aL[2];
            #pragma unroll
            for (int s = 0; s < 2; s++) {
                int idx = ((mw*2 + s)*4 + kt)*32 + lane;
                aH[s] = sA[idx];
                aL[s] = sA[1024 + idx];
            }
            #pragma unroll
            for (int j = 0; j < 4; j++) {
                int idx = nh*2048 + ((npbase + j)*4 + kt)*32 + lane;
                uint4 bH = Bcur[idx];
                uint4 bL = Bcur[1024 + idx];
                #pragma unroll
                for (int s = 0; s < 2; s++) {
                    mma16816(acc1[s][2*j],   aH[s], bH.x, bH.y);
                    mma16816(acc1[s][2*j+1], aH[s], bH.z, bH.w);
                    mma16816(acc1[s][2*j],   aH[s], bL.x, bL.y);
                    mma16816(acc1[s][2*j+1], aH[s], bL.z, bL.w);
                    mma16816(acc1[s][2*j],   aL[s], bH.x, bH.y);
                    mma16816(acc1[s][2*j+1], aL[s], bH.z, bH.w);
                }
            }
        }
    }
    __syncthreads();

    // prefetch GEMM2 B(0) into sA region
    {
        const uint4* gB = g_w2img + ((size_t)(layer*4 + 0)*2) * 1024;
        #pragma unroll
        for (int i = 0; i < 4; i++) cpasync16(&sA[tid + i*512], &gB[tid + i*512]);
        CP_COMMIT;
    }

    // ---- epilogue 1: silu + split -> h fragments ----
    #pragma unroll
    for (int s = 0; s < 2; s++)
        #pragma unroll
        for (int nt = 0; nt < 8; nt++) {
            float c0 = acc1[s][nt][0], c1 = acc1[s][nt][1];
            float c2 = acc1[s][nt][2], c3 = acc1[s][nt][3];
            c0 = c0 / (1.f + __expf(-c0));
            c1 = c1 / (1.f + __expf(-c1));
            c2 = c2 / (1.f + __expf(-c2));
            c3 = c3 / (1.f + __expf(-c3));
            int R = mw*32 + s*16 + g;
            int C = nw*64 + (nt >> 1)*16 + (nt & 1)*8 + tg*2;
            u32 hi01, lo01, hi23, lo23;
            split2(c0, c1, hi01, lo01);
            split2(c2, c3, hi23, lo23);
            int mtp  = R >> 4;
            int ktp  = C >> 4;
            int khal = (C >> 3) & 1;
            int lanep = g*4 + tg;
            u32 base = (((u32)(mtp*16 + ktp)*32 + lanep) << 2);
            hsw[base + 2*khal]             = hi01;
            hsw[base + 2*khal + 1]         = hi23;
            hsw[16384 + base + 2*khal]     = lo01;
            hsw[16384 + base + 2*khal + 1] = lo23;
        }
    CP_WAIT0;
    __syncthreads();

    // ===================== GEMM2 =====================
    float acc2[2][4][4];
    #pragma unroll
    for (int s = 0; s < 2; s++)
        #pragma unroll
        for (int j = 0; j < 4; j++)
            #pragma unroll
            for (int q = 0; q < 4; q++) acc2[s][j][q] = 0.f;

    uint4* B2[2] = { (uint4*)(smem + 131072), (uint4*)(smem + 163840) };
    for (int ch = 0; ch < 4; ch++) {
        if (ch < 3) {
            const uint4* gB = g_w2img + ((size_t)(layer*4 + ch + 1)*2) * 1024;
            uint4* Bnx = B2[(ch+1) & 1];
            #pragma unroll
            for (int i = 0; i < 4; i++) cpasync16(&Bnx[tid + i*512], &gB[tid + i*512]);
            CP_COMMIT;
        }
        const uint4* Bcur = B2[ch & 1];
        #pragma unroll
        for (int kt = 0; kt < 4; kt++) {
            int ktg = ch*4 + kt;
            uint4 aH[2], aL[2];
            #pragma unroll
            for (int s = 0; s < 2; s++) {
                int idx = ((mw*2 + s)*16 + ktg)*32 + lane;
                aH[s] = hs4[idx];
                aL[s] = hs4[4096 + idx];
            }
            #pragma unroll
            for (int j = 0; j < 2; j++) {
                int idx = ((nw*2 + j)*4 + kt)*32 + lane;
                uint4 bH = Bcur[idx];
                uint4 bL = Bcur[1024 + idx];
                #pragma unroll
                for (int s = 0; s < 2; s++) {
                    mma16816(acc2[s][2*j],   aH[s], bH.x, bH.y);
                    mma16816(acc2[s][2*j+1], aH[s], bH.z, bH.w);
                    mma16816(acc2[s][2*j],   aH[s], bL.x, bL.y);
                    mma16816(acc2[s][2*j+1], aH[s], bL.z, bL.w);
                    mma16816(acc2[s][2*j],   aL[s], bH.x, bH.y);
                    mma16816(acc2[s][2*j+1], aL[s], bH.z, bH.w);
                }
            }
        }
        if (ch < 3) { CP_WAIT0; __syncthreads(); }
    }

    #pragma unroll
    for (int s = 0; s < 2; s++)
        #pragma unroll
        for (int nt = 0; nt < 4; nt++) {
            int R = mw*32 + s*16 + g;
            int C = nw*32 + (nt >> 1)*16 + (nt & 1)*8 + tg*2;
            float2 v0 = make_float2(acc2[s][nt][0], acc2[s][nt][1]);
            float2 v1 = make_float2(acc2[s][nt][2], acc2[s][nt][3]);
            *(float2*)&g_m[(size_t)(e0 + R)*CCH + C]     = v0;
            *(float2*)&g_m[(size_t)(e0 + R + 8)*CCH + C] = v1;
        }
}

// ---------------- k_agg ----------------
__global__ void k_agg() {
    int n = blockIdx.x, tid = threadIdx.x;
    __shared__ float mS[NBR*CCH];
    __shared__ float yS[NBR*KH];
    int eb = n*NBR;
    for (int i = tid; i < NBR*CCH; i += 128) mS[i] = g_m[(size_t)eb*CCH + i];
    for (int i = tid; i < NBR*KH;  i += 128) yS[i] = g_Y[(size_t)eb*KH + i];
    __syncthreads();
    int c = tid;
    float acc[KH];
    #pragma unroll
    for (int k = 0; k < KH; k++) acc[k] = 0.f;
    #pragma unroll
    for (int e = 0; e < NBR; e++) {
        float mv = mS[e*CCH + c];
        #pragma unroll
        for (int k = 0; k < KH; k++) acc[k] = fmaf(yS[e*KH + k], mv, acc[k]);
    }
    #pragma unroll
    for (int k = 0; k < KH; k++) g_x[((size_t)n*KH + k)*CCH + c] += acc[k]*0.05f;
}

// ---------------- k_hw ----------------
__global__ void k_hw(const float* __restrict__ wf) {
    int n = blockIdx.x, lane = threadIdx.x;
    float v = 0.f;
    for (int c = lane; c < CCH; c += 32) v += g_x[(size_t)n*(KH*CCH) + c]*wf[c];
    #pragma unroll
    for (int off = 16; off; off >>= 1) v += __shfl_xor_sync(0xffffffffu, v, off);
    if (lane == 0) g_hw[n] = v;
}

// ---------------- k_out ----------------
__global__ void k_out(const float* __restrict__ Wa, const float* __restrict__ ba,
                      const int* __restrict__ ei, float* __restrict__ out) {
    int n = blockIdx.x, tid = threadIdx.x;
    __shared__ float hs[CCH];
    hs[tid] = g_x[(size_t)n*(KH*CCH) + tid];
    __syncthreads();
    if (tid < 100) {
        float acc = ba[tid];
        for (int c = 0; c < CCH; c++) acc = fmaf(hs[c], Wa[c*100 + tid], acc);
        out[NATOM*3 + n*100 + tid] = acc;
    } else if (tid < 103) {
        int j = tid - 100;
        float hwn = g_hw[n];
        float acc = 0.f;
        for (int e = 0; e < NBR; e++) {
            int ge = n*NBR + e;
            acc = fmaf(g_hw[ei[ge]] - hwn, g_dirn[ge*3 + j], acc);
        }
        out[n*3 + j] = acc;
    }
}

// ---------------- launch ----------------
static const int SMEM_S = (XS_F + YS_F)*4 + 640*4;

extern "C" void kernel_launch(void* const* d_in, const int* in_sizes, int n_in,
                              void* d_out, int out_size) {
    const float* z       = (const float*)d_in[0];
    const float* frac    = (const float*)d_in[1];
    const int*   types   = (const int*)  d_in[2];
    const float* lengths = (const float*)d_in[4];
    const float* angles  = (const float*)d_in[5];
    const int*   ei      = (const int*)  d_in[7];
    const float* emb     = (const float*)d_in[8];
    const float* zproj   = (const float*)d_in[9];
    const float* Wd      = (const float*)d_in[10];
    const float* W1      = (const float*)d_in[11];
    const float* W2      = (const float*)d_in[12];
    const float* Wa      = (const float*)d_in[13];
    const float* ba      = (const float*)d_in[14];
    const float* wf      = (const float*)d_in[15];
    float* out = (float*)d_out;

    cudaFuncSetAttribute(k_s,   cudaFuncAttributeMaxDynamicSharedMemorySize, SMEM_S);
    cudaFuncSetAttribute(k_mlp, cudaFuncAttributeMaxDynamicSharedMemorySize, SM_MLP);

    k_init <<<NCRYST, 512>>>(z, frac, lengths, angles, zproj, types, emb, ei);   // 0
    k_wconv<<<384, 256>>>(W1, Wd, W2);                                           // 1
    for (int l = 0; l < NLAYER; l++) {
        k_s  <<<dim3(8, NCRYST), 256, SMEM_S>>>(ei);                             // 2 (l=0)
        k_mlp<<<NCTA_MLP, 512, SM_MLP>>>(l);                                     // 3 (l=0) -> profiled
        k_agg<<<NATOM, 128>>>();
    }
    k_hw <<<NATOM, 32>>>(wf);
    k_out<<<NATOM, 128>>>(Wa, ba, ei, out);
}

// round 10
// speedup vs baseline: 2.8096x; 1.0396x over previous
#include <cuda_runtime.h>
#include <cuda_bf16.h>
#include <math.h>
#include <stdint.h>

#define NCRYST 64
#define ATOMS  32
#define NATOM  2048
#define NBR    20
#define NEDGE  40960
#define CCH    128
#define HID    256
#define NBIN   128
#define NLAYER 8
#define KH     19
#define NCTA_MLP (NEDGE/128)     // 320

typedef unsigned long long u64;
typedef unsigned int u32;

// ---------------- scratch ----------------
__device__ float g_dirn[NEDGE * 3];
__device__ float g_Y   [NEDGE * KH];
__device__ float g_rbf [NEDGE * NBIN];
__device__ float g_x   [NATOM * KH * CCH];
__device__ float g_s   [NEDGE * CCH];
__device__ float g_m   [NEDGE * CCH];
__device__ float g_hw  [NATOM];
__device__ uint4 g_w1img[8*2*4*2*1024];          // 2 MB
__device__ uint4 g_w2img[8*4*2*1024];            // 1 MB
__device__ uint4 g_aimg [NCTA_MLP*4*2*1024];     // rbf chunks 2,3 used

// ---------------- helpers ----------------
__device__ __forceinline__ u32 s2u(const void* p){ return (u32)__cvta_generic_to_shared(p); }
__device__ __forceinline__ void cpasync16(void* dst, const void* src){
    asm volatile("cp.async.cg.shared.global [%0], [%1], 16;" :: "r"(s2u(dst)), "l"(src));
}
#define CP_COMMIT asm volatile("cp.async.commit_group;" ::: "memory")
#define CP_WAIT0  asm volatile("cp.async.wait_group 0;" ::: "memory")
#define CP_WAIT1  asm volatile("cp.async.wait_group 1;" ::: "memory")

__device__ __forceinline__ void split2(float v0, float v1, u32& hi, u32& lo){
    __nv_bfloat16 h0 = __float2bfloat16_rn(v0);
    __nv_bfloat16 h1 = __float2bfloat16_rn(v1);
    float l0 = v0 - __bfloat162float(h0);
    float l1 = v1 - __bfloat162float(h1);
    __nv_bfloat162 H; H.x = h0; H.y = h1;
    __nv_bfloat162 L = __floats2bfloat162_rn(l0, l1);
    hi = *(u32*)&H; lo = *(u32*)&L;
}

__device__ __forceinline__ void mma16816(float* c, const uint4 a, const u32 b0, const u32 b1){
    asm volatile("mma.sync.aligned.m16n8k16.row.col.f32.bf16.bf16.f32 "
        "{%0,%1,%2,%3}, {%4,%5,%6,%7}, {%8,%9}, {%0,%1,%2,%3};"
        : "+f"(c[0]), "+f"(c[1]), "+f"(c[2]), "+f"(c[3])
        : "r"(a.x), "r"(a.y), "r"(a.z), "r"(a.w), "r"(b0), "r"(b1));
}

// ---------------- k_init ----------------
__global__ __launch_bounds__(512) void k_init(
        const float* __restrict__ z, const float* __restrict__ frac,
        const float* __restrict__ lengths, const float* __restrict__ angles,
        const float* __restrict__ zproj, const int* __restrict__ types,
        const float* __restrict__ emb, const int* __restrict__ ei) {
    int cb = blockIdx.x, tid = threadIdx.x;
    __shared__ float lats[9];
    __shared__ float zs[256];
    __shared__ float poss[ATOMS*3];
    __shared__ float zcs[CCH];
    __shared__ float ds[640];
    int abase = cb*ATOMS;
    int ebase = cb*640;

    if (tid == 0) {
        float a = lengths[cb*3+0], b = lengths[cb*3+1], c = lengths[cb*3+2];
        const float D2R = 0.017453292519943295f;
        float r0 = angles[cb*3+0]*D2R, r1 = angles[cb*3+1]*D2R, r2 = angles[cb*3+2]*D2R;
        float ca = cosf(r0), cbta = cosf(r1), cg = cosf(r2), sg = sinf(r2);
        float v3y = (ca - cbta*cg)/sg;
        float t = 1.0f - cbta*cbta - v3y*v3y;
        if (t < 1e-8f) t = 1e-8f;
        float v3z = sqrtf(t);
        lats[0]=a;        lats[1]=0.f;     lats[2]=0.f;
        lats[3]=b*cg;     lats[4]=b*sg;    lats[5]=0.f;
        lats[6]=c*cbta;   lats[7]=c*v3y;   lats[8]=c*v3z;
    }
    if (tid < 256) zs[tid] = z[cb*256 + tid];
    __syncthreads();
    if (tid < 96) {
        int a = tid/3, j = tid%3;
        int n = abase + a;
        poss[a*3+j] = frac[n*3+0]*lats[0+j] + frac[n*3+1]*lats[3+j] + frac[n*3+2]*lats[6+j];
    }
    if (tid < 128) {
        float acc = 0.f;
        for (int i = 0; i < 256; i++) acc += zs[i]*zproj[i*CCH + tid];
        zcs[tid] = acc;
    }
    __syncthreads();

    for (int i = tid; i < ATOMS*CCH; i += 512) {
        int a = i >> 7, c = i & 127;
        int n = abase + a;
        g_x[(size_t)(n*KH)*CCH + c] = emb[types[n]*CCH + c] + zcs[c];
    }
    for (int i4 = tid; i4 < ATOMS*18*CCH/4; i4 += 512) {
        int flat = i4*4;
        int a = flat/(18*CCH);
        int r = flat - a*(18*CCH);
        int k = 1 + (r >> 7), c = r & 127;
        *(float4*)&g_x[((size_t)(abase+a)*KH + k)*CCH + c] = make_float4(0.f,0.f,0.f,0.f);
    }

    for (int e = tid; e < 640; e += 512) {
        int s = ei[ebase + e] - abase, d = ei[NEDGE + ebase + e] - abase;
        float vx = poss[s*3+0]-poss[d*3+0];
        float vy = poss[s*3+1]-poss[d*3+1];
        float vz = poss[s*3+2]-poss[d*3+2];
        float dist = sqrtf(vx*vx + vy*vy + vz*vz) + 1e-8f;
        ds[e] = dist;
        float dx = vx/dist, dy = vy/dist, dz = vz/dist;
        int ge = ebase + e;
        g_dirn[ge*3+0]=dx; g_dirn[ge*3+1]=dy; g_dirn[ge*3+2]=dz;
        float ct = dz;
        float rho = sqrtf(dx*dx + dy*dy) + 1e-12f;
        float cph = dx/rho, sph = dy/rho;
        float P0[7]; P0[0]=1.f; P0[1]=ct;
        #pragma unroll
        for (int l=2;l<=6;l++) P0[l] = ((2*l-1)*ct*P0[l-1] - (l-1)*P0[l-2]) / l;
        float P1[7]; P1[0]=0.f; P1[1]=-rho; P1[2]=-3.f*ct*rho;
        #pragma unroll
        for (int l=3;l<=6;l++) P1[l] = ((2*l-1)*ct*P1[l-1] - l*P1[l-2]) / (l-1);
        float* Yp = &g_Y[(size_t)ge*KH];
        const float FPI = 12.566370614359172f;
        Yp[0] = 0.28209479177387814f;
        int idx = 1;
        #pragma unroll
        for (int l=1;l<=6;l++) {
            float K0 = sqrtf((2*l+1)/FPI);
            float K1 = sqrtf(2.f*(2*l+1)/(FPI*l*(l+1)));
            Yp[idx++] = K1*P1[l]*sph;
            Yp[idx++] = K0*P0[l];
            Yp[idx++] = K1*P1[l]*cph;
        }
    }
    __syncthreads();

    const float step = 8.0f/127.0f;
    const float inv  = 127.0f/8.0f;
    for (int i = tid; i < 640*NBIN; i += 512) {
        int e = i >> 7, bin = i & 127;
        float t = (ds[e] - step*(float)bin)*inv;
        g_rbf[(size_t)(ebase+e)*NBIN + bin] = expf(-0.5f*t*t);
    }
    __syncthreads();

    for (int i = tid; i < 5*2*1024; i += 512) {
        int lc  = i >> 11;
        int r   = i & 2047;
        int chl = r >> 10;
        int w   = r & 1023;
        int cta = cb*5 + lc;
        int mt = w >> 7, ktl = (w >> 5) & 3, lane = w & 31;
        int m0 = mt*16 + (lane >> 2);
        int kk = chl*64 + ktl*16 + (lane & 3)*2;
        size_t row0 = (size_t)(cta*128 + m0) * NBIN;
        size_t row1 = row0 + 8*NBIN;
        float2 p00 = *(const float2*)&g_rbf[row0 + kk];
        float2 p10 = *(const float2*)&g_rbf[row1 + kk];
        float2 p01 = *(const float2*)&g_rbf[row0 + kk + 8];
        float2 p11 = *(const float2*)&g_rbf[row1 + kk + 8];
        uint4 hi, lo;
        split2(p00.x, p00.y, hi.x, lo.x);
        split2(p10.x, p10.y, hi.y, lo.y);
        split2(p01.x, p01.y, hi.z, lo.z);
        split2(p11.x, p11.y, hi.w, lo.w);
        size_t base = ((size_t)(cta*4 + chl + 2)*2) * 1024 + w;
        g_aimg[base]        = hi;
        g_aimg[base + 1024] = lo;
    }
}

// ---------------- k_wconv ----------------
__global__ void k_wconv(const float* __restrict__ W1, const float* __restrict__ Wd,
                        const float* __restrict__ W2) {
    int t = blockIdx.x * 256 + threadIdx.x;
    if (t < 65536) {
        int l  = t >> 13;
        int r  = t & 8191;
        int nh = r >> 12;
        int ch = (r >> 10) & 3;
        int w  = r & 1023;
        int np = w >> 7, ktl = (w >> 5) & 3, lane = w & 31;
        int nE = nh*128 + np*16 + (lane >> 2);
        int nO = nE + 8;
        int k0 = ch*64 + ktl*16 + (lane & 3)*2;
        float v[8];
        #pragma unroll
        for (int q = 0; q < 4; q++) {
            int n = (q < 2) ? nE : nO;
            int kk = k0 + ((q & 1) ? 8 : 0);
            float a0, a1;
            if (kk < 128) { a0 = W1[l*32768 + kk*256 + n];       a1 = W1[l*32768 + (kk+1)*256 + n]; }
            else          { a0 = Wd[l*32768 + (kk-128)*256 + n]; a1 = Wd[l*32768 + (kk-127)*256 + n]; }
            v[q*2] = a0; v[q*2+1] = a1;
        }
        uint4 hi, lo;
        split2(v[0], v[1], hi.x, lo.x);
        split2(v[2], v[3], hi.y, lo.y);
        split2(v[4], v[5], hi.z, lo.z);
        split2(v[6], v[7], hi.w, lo.w);
        size_t base = ((size_t)((l*2 + nh)*4 + ch)*2) * 1024 + w;
        g_w1img[base]        = hi;
        g_w1img[base + 1024] = lo;
    } else if (t < 98304) {
        int u  = t - 65536;
        int l  = u >> 12;
        int ch = (u >> 10) & 3;
        int w  = u & 1023;
        int np = w >> 7, ktl = (w >> 5) & 3, lane = w & 31;
        int nE = np*16 + (lane >> 2);
        int nO = nE + 8;
        int k0 = ch*64 + ktl*16 + (lane & 3)*2;
        float v[8];
        #pragma unroll
        for (int q = 0; q < 4; q++) {
            int n = (q < 2) ? nE : nO;
            int kk = k0 + ((q & 1) ? 8 : 0);
            v[q*2]   = W2[l*32768 + kk*128 + n];
            v[q*2+1] = W2[l*32768 + (kk+1)*128 + n];
        }
        uint4 hi, lo;
        split2(v[0], v[1], hi.x, lo.x);
        split2(v[2], v[3], hi.y, lo.y);
        split2(v[4], v[5], hi.z, lo.z);
        split2(v[6], v[7], hi.w, lo.w);
        size_t base = ((size_t)(l*4 + ch)*2) * 1024 + w;
        g_w2img[base]        = hi;
        g_w2img[base + 1024] = lo;
    }
}

// ---------------- k_s ----------------
#define XS_STRIDE 20
#define XS_F (ATOMS*KH*XS_STRIDE)
#define YS_F (640*KH)
__global__ __launch_bounds__(256, 2) void k_s(const int* __restrict__ ei) {
    int cq = blockIdx.x;
    int cb = blockIdx.y;
    int tid = threadIdx.x;
    extern __shared__ float sm[];
    float* xs  = sm;
    float* Ys  = sm + XS_F;
    int*  srcs = (int*)(Ys + YS_F);
    int abase = cb*ATOMS;
    int c0 = cq*16;
    for (int i = tid; i < ATOMS*KH*16; i += 256) {
        int a = i/(KH*16); int r = i - a*(KH*16); int k = r >> 4; int c = r & 15;
        xs[(a*KH + k)*XS_STRIDE + c] = g_x[((size_t)(abase+a)*KH + k)*CCH + c0 + c];
    }
    int ebase = cb*640;
    for (int i = tid; i < YS_F; i += 256) Ys[i] = g_Y[(size_t)ebase*KH + i];
    for (int i = tid; i < 640; i += 256) srcs[i] = ei[ebase + i] - abase;
    __syncthreads();
    int cg = tid & 3, er = tid >> 2;
    #pragma unroll 2
    for (int j = 0; j < 10; j++) {
        int e = j*64 + er;
        int sl = srcs[e];
        const float* xr = &xs[sl*(KH*XS_STRIDE) + cg*4];
        const float* yr = &Ys[e*KH];
        float4 acc = make_float4(0.f, 0.f, 0.f, 0.f);
        #pragma unroll
        for (int k = 0; k < KH; k++) {
            float y = yr[k];
            float4 xv = *(const float4*)&xr[k*XS_STRIDE];
            acc.x = fmaf(y, xv.x, acc.x);
            acc.y = fmaf(y, xv.y, acc.y);
            acc.z = fmaf(y, xv.z, acc.z);
            acc.w = fmaf(y, xv.w, acc.w);
        }
        *(float4*)&g_s[(size_t)(ebase+e)*CCH + c0 + cg*4] = acc;
    }
}

// ---------------- k_mlp: 512 thr, hoisted LDG + full A/B double-buffer ----------------
#define SM_MLP   196608

__global__ __launch_bounds__(512, 1) void k_mlp(int layer) {
    extern __shared__ char smem[];
    int tid = threadIdx.x;
    int wid = tid >> 5, lane = tid & 31;
    int mw = wid & 3, nw = wid >> 2;       // 4 x 4
    int cta = blockIdx.x;
    int e0 = cta * 128;
    int g  = lane >> 2;
    int tg = lane & 3;

    uint4* Bb0 = (uint4*)smem;             // 64 KB
    uint4* Bb1 = (uint4*)(smem + 65536);
    uint4* sA0 = (uint4*)(smem + 131072);  // 32 KB
    uint4* sA1 = (uint4*)(smem + 163840);  // 32 KB
    uint4* hs4 = (uint4*)smem;
    u32*   hsw = (u32*)smem;

    int nh     = nw >> 1;
    int npbase = (nw & 1) * 4;

    // ---- 0: hoist all s-operand LDGs into registers ----
    float2 sv[2][2][4];
    #pragma unroll
    for (int it = 0; it < 2; it++) {
        int w = tid + it*512;
        int mt = w >> 7, ktl = (w >> 5) & 3, ln = w & 31;
        int m0 = mt*16 + (ln >> 2);
        int kkb = ktl*16 + (ln & 3)*2;
        size_t row0 = (size_t)(e0 + m0)*CCH;
        size_t row1 = row0 + 8*CCH;
        #pragma unroll
        for (int ch = 0; ch < 2; ch++) {
            int kk = ch*64 + kkb;
            sv[ch][it][0] = *(const float2*)&g_s[row0 + kk];
            sv[ch][it][1] = *(const float2*)&g_s[row1 + kk];
            sv[ch][it][2] = *(const float2*)&g_s[row0 + kk + 8];
            sv[ch][it][3] = *(const float2*)&g_s[row1 + kk + 8];
        }
    }

    // ---- fill B(0) ----
    {
        const uint4* b0 = g_w1img + ((size_t)((layer*2 + 0)*4 + 0)*2) * 1024;
        const uint4* b1 = g_w1img + ((size_t)((layer*2 + 1)*4 + 0)*2) * 1024;
        #pragma unroll
        for (int i = 0; i < 4; i++) cpasync16(&Bb0[tid + i*512],        &b0[tid + i*512]);
        #pragma unroll
        for (int i = 0; i < 4; i++) cpasync16(&Bb0[2048 + tid + i*512], &b1[tid + i*512]);
        CP_COMMIT;   // g1
    }
    // ---- convert s regs -> sA0 (ch0), sA1 (ch1) ----
    #pragma unroll
    for (int ch = 0; ch < 2; ch++) {
        uint4* dst = ch ? sA1 : sA0;
        #pragma unroll
        for (int it = 0; it < 2; it++) {
            int w = tid + it*512;
            uint4 hi, lo;
            split2(sv[ch][it][0].x, sv[ch][it][0].y, hi.x, lo.x);
            split2(sv[ch][it][1].x, sv[ch][it][1].y, hi.y, lo.y);
            split2(sv[ch][it][2].x, sv[ch][it][2].y, hi.z, lo.z);
            split2(sv[ch][it][3].x, sv[ch][it][3].y, hi.w, lo.w);
            dst[w]        = hi;
            dst[1024 + w] = lo;
        }
    }
    // ---- fill B(1) ----
    {
        const uint4* b0 = g_w1img + ((size_t)((layer*2 + 0)*4 + 1)*2) * 1024;
        const uint4* b1 = g_w1img + ((size_t)((layer*2 + 1)*4 + 1)*2) * 1024;
        #pragma unroll
        for (int i = 0; i < 4; i++) cpasync16(&Bb1[tid + i*512],        &b0[tid + i*512]);
        #pragma unroll
        for (int i = 0; i < 4; i++) cpasync16(&Bb1[2048 + tid + i*512], &b1[tid + i*512]);
        CP_COMMIT;   // g2
    }

    float acc1[2][8][4];
    #pragma unroll
    for (int s = 0; s < 2; s++)
        #pragma unroll
        for (int j = 0; j < 8; j++)
            #pragma unroll
            for (int q = 0; q < 4; q++) acc1[s][j][q] = 0.f;

    #define G1_COMPUTE(Acur, Bcur)                                               \
    {                                                                            \
        _Pragma("unroll")                                                        \
        for (int kt = 0; kt < 4; kt++) {                                         \
            uint4 aH[2], aL[2];                                                  \
            _Pragma("unroll")                                                    \
            for (int s = 0; s < 2; s++) {                                        \
                int idx = ((mw*2 + s)*4 + kt)*32 + lane;                         \
                aH[s] = (Acur)[idx];                                             \
                aL[s] = (Acur)[1024 + idx];                                      \
            }                                                                    \
            _Pragma("unroll")                                                    \
            for (int j = 0; j < 4; j++) {                                        \
                int idx = nh*2048 + ((npbase + j)*4 + kt)*32 + lane;             \
                uint4 bH = (Bcur)[idx];                                          \
                uint4 bL = (Bcur)[1024 + idx];                                   \
                _Pragma("unroll")                                                \
                for (int s = 0; s < 2; s++) {                                    \
                    mma16816(acc1[s][2*j],   aH[s], bH.x, bH.y);                 \
                    mma16816(acc1[s][2*j+1], aH[s], bH.z, bH.w);                 \
                    mma16816(acc1[s][2*j],   aH[s], bL.x, bL.y);                 \
                    mma16816(acc1[s][2*j+1], aH[s], bL.z, bL.w);                 \
                    mma16816(acc1[s][2*j],   aL[s], bH.x, bH.y);                 \
                    mma16816(acc1[s][2*j+1], aL[s], bH.z, bH.w);                 \
                }                                                                \
            }                                                                    \
        }                                                                        \
    }

    #define FILL_B1(ch, Bp)                                                          \
    {                                                                                \
        const uint4* b0 = g_w1img + ((size_t)((layer*2 + 0)*4 + (ch))*2) * 1024;     \
        const uint4* b1 = g_w1img + ((size_t)((layer*2 + 1)*4 + (ch))*2) * 1024;     \
        _Pragma("unroll")                                                            \
        for (int i = 0; i < 4; i++) cpasync16(&(Bp)[tid + i*512],        &b0[tid + i*512]); \
        _Pragma("unroll")                                                            \
        for (int i = 0; i < 4; i++) cpasync16(&(Bp)[2048 + tid + i*512], &b1[tid + i*512]); \
    }
    #define FILL_A(ch, Ap)                                                           \
    {                                                                                \
        const uint4* gA = g_aimg + ((size_t)(cta*4 + (ch))*2) * 1024;                \
        _Pragma("unroll")                                                            \
        for (int i = 0; i < 4; i++) cpasync16(&(Ap)[tid + i*512], &gA[tid + i*512]); \
    }

    CP_WAIT1; __syncthreads();          // B(0) ready
    G1_COMPUTE(sA0, Bb0);               // ch 0
    __syncthreads();
    FILL_A(2, sA0); FILL_B1(2, Bb0); CP_COMMIT;   // g3
    CP_WAIT1; __syncthreads();          // B(1) ready
    G1_COMPUTE(sA1, Bb1);               // ch 1
    __syncthreads();
    FILL_A(3, sA1); FILL_B1(3, Bb1); CP_COMMIT;   // g4
    CP_WAIT1; __syncthreads();          // A(2)/B(2) ready
    G1_COMPUTE(sA0, Bb0);               // ch 2
    __syncthreads();
    {   // prefetch GEMM2 B(0) into sA0 (free after ch2)
        const uint4* gB = g_w2img + ((size_t)(layer*4 + 0)*2) * 1024;
        #pragma unroll
        for (int i = 0; i < 4; i++) cpasync16(&sA0[tid + i*512], &gB[tid + i*512]);
        CP_COMMIT;   // g5
    }
    CP_WAIT1; __syncthreads();          // A(3)/B(3) ready
    G1_COMPUTE(sA1, Bb1);               // ch 3
    __syncthreads();                    // Bb region free -> h storage

    // ---- epilogue 1: silu + split -> h fragments ----
    #pragma unroll
    for (int s = 0; s < 2; s++)
        #pragma unroll
        for (int nt = 0; nt < 8; nt++) {
            float c0 = acc1[s][nt][0], c1 = acc1[s][nt][1];
            float c2 = acc1[s][nt][2], c3 = acc1[s][nt][3];
            c0 = c0 / (1.f + __expf(-c0));
            c1 = c1 / (1.f + __expf(-c1));
            c2 = c2 / (1.f + __expf(-c2));
            c3 = c3 / (1.f + __expf(-c3));
            int R = mw*32 + s*16 + g;
            int C = nw*64 + (nt >> 1)*16 + (nt & 1)*8 + tg*2;
            u32 hi01, lo01, hi23, lo23;
            split2(c0, c1, hi01, lo01);
            split2(c2, c3, hi23, lo23);
            int mtp  = R >> 4;
            int ktp  = C >> 4;
            int khal = (C >> 3) & 1;
            int lanep = g*4 + tg;
            u32 base = (((u32)(mtp*16 + ktp)*32 + lanep) << 2);
            hsw[base + 2*khal]             = hi01;
            hsw[base + 2*khal + 1]         = hi23;
            hsw[16384 + base + 2*khal]     = lo01;
            hsw[16384 + base + 2*khal + 1] = lo23;
        }
    CP_WAIT0;
    __syncthreads();

    // ===================== GEMM2 =====================
    float acc2[2][4][4];
    #pragma unroll
    for (int s = 0; s < 2; s++)
        #pragma unroll
        for (int j = 0; j < 4; j++)
            #pragma unroll
            for (int q = 0; q < 4; q++) acc2[s][j][q] = 0.f;

    uint4* B2[2] = { sA0, sA1 };
    for (int ch = 0; ch < 4; ch++) {
        if (ch < 3) {
            const uint4* gB = g_w2img + ((size_t)(layer*4 + ch + 1)*2) * 1024;
            uint4* Bnx = B2[(ch+1) & 1];
            #pragma unroll
            for (int i = 0; i < 4; i++) cpasync16(&Bnx[tid + i*512], &gB[tid + i*512]);
            CP_COMMIT;
        }
        const uint4* Bcur = B2[ch & 1];
        #pragma unroll
        for (int kt = 0; kt < 4; kt++) {
            int ktg = ch*4 + kt;
            uint4 aH[2], aL[2];
            #pragma unroll
            for (int s = 0; s < 2; s++) {
                int idx = ((mw*2 + s)*16 + ktg)*32 + lane;
                aH[s] = hs4[idx];
                aL[s] = hs4[4096 + idx];
            }
            #pragma unroll
            for (int j = 0; j < 2; j++) {
                int idx = ((nw*2 + j)*4 + kt)*32 + lane;
                uint4 bH = Bcur[idx];
                uint4 bL = Bcur[1024 + idx];
                #pragma unroll
                for (int s = 0; s < 2; s++) {
                    mma16816(acc2[s][2*j],   aH[s], bH.x, bH.y);
                    mma16816(acc2[s][2*j+1], aH[s], bH.z, bH.w);
                    mma16816(acc2[s][2*j],   aH[s], bL.x, bL.y);
                    mma16816(acc2[s][2*j+1], aH[s], bL.z, bL.w);
                    mma16816(acc2[s][2*j],   aL[s], bH.x, bH.y);
                    mma16816(acc2[s][2*j+1], aL[s], bH.z, bH.w);
                }
            }
        }
        if (ch < 3) { CP_WAIT0; __syncthreads(); }
    }

    #pragma unroll
    for (int s = 0; s < 2; s++)
        #pragma unroll
        for (int nt = 0; nt < 4; nt++) {
            int R = mw*32 + s*16 + g;
            int C = nw*32 + (nt >> 1)*16 + (nt & 1)*8 + tg*2;
            float2 v0 = make_float2(acc2[s][nt][0], acc2[s][nt][1]);
            float2 v1 = make_float2(acc2[s][nt][2], acc2[s][nt][3]);
            *(float2*)&g_m[(size_t)(e0 + R)*CCH + C]     = v0;
            *(float2*)&g_m[(size_t)(e0 + R + 8)*CCH + C] = v1;
        }
}

// ---------------- k_agg ----------------
__global__ void k_agg() {
    int n = blockIdx.x, tid = threadIdx.x;
    __shared__ float mS[NBR*CCH];
    __shared__ float yS[NBR*KH];
    int eb = n*NBR;
    for (int i = tid; i < NBR*CCH; i += 128) mS[i] = g_m[(size_t)eb*CCH + i];
    for (int i = tid; i < NBR*KH;  i += 128) yS[i] = g_Y[(size_t)eb*KH + i];
    __syncthreads();
    int c = tid;
    float acc[KH];
    #pragma unroll
    for (int k = 0; k < KH; k++) acc[k] = 0.f;
    #pragma unroll
    for (int e = 0; e < NBR; e++) {
        float mv = mS[e*CCH + c];
        #pragma unroll
        for (int k = 0; k < KH; k++) acc[k] = fmaf(yS[e*KH + k], mv, acc[k]);
    }
    #pragma unroll
    for (int k = 0; k < KH; k++) g_x[((size_t)n*KH + k)*CCH + c] += acc[k]*0.05f;
}

// ---------------- k_hw ----------------
__global__ void k_hw(const float* __restrict__ wf) {
    int n = blockIdx.x, lane = threadIdx.x;
    float v = 0.f;
    for (int c = lane; c < CCH; c += 32) v += g_x[(size_t)n*(KH*CCH) + c]*wf[c];
    #pragma unroll
    for (int off = 16; off; off >>= 1) v += __shfl_xor_sync(0xffffffffu, v, off);
    if (lane == 0) g_hw[n] = v;
}

// ---------------- k_out ----------------
__global__ void k_out(const float* __restrict__ Wa, const float* __restrict__ ba,
                      const int* __restrict__ ei, float* __restrict__ out) {
    int n = blockIdx.x, tid = threadIdx.x;
    __shared__ float hs[CCH];
    hs[tid] = g_x[(size_t)n*(KH*CCH) + tid];
    __syncthreads();
    if (tid < 100) {
        float acc = ba[tid];
        for (int c = 0; c < CCH; c++) acc = fmaf(hs[c], Wa[c*100 + tid], acc);
        out[NATOM*3 + n*100 + tid] = acc;
    } else if (tid < 103) {
        int j = tid - 100;
        float hwn = g_hw[n];
        float acc = 0.f;
        for (int e = 0; e < NBR; e++) {
            int ge = n*NBR + e;
            acc = fmaf(g_hw[ei[ge]] - hwn, g_dirn[ge*3 + j], acc);
        }
        out[n*3 + j] = acc;
    }
}

// ---------------- launch ----------------
static const int SMEM_S = (XS_F + YS_F)*4 + 640*4;

extern "C" void kernel_launch(void* const* d_in, const int* in_sizes, int n_in,
                              void* d_out, int out_size) {
    const float* z       = (const float*)d_in[0];
    const float* frac    = (const float*)d_in[1];
    const int*   types   = (const int*)  d_in[2];
    const float* lengths = (const float*)d_in[4];
    const float* angles  = (const float*)d_in[5];
    const int*   ei      = (const int*)  d_in[7];
    const float* emb     = (const float*)d_in[8];
    const float* zproj   = (const float*)d_in[9];
    const float* Wd      = (const float*)d_in[10];
    const float* W1      = (const float*)d_in[11];
    const float* W2      = (const float*)d_in[12];
    const float* Wa      = (const float*)d_in[13];
    const float* ba      = (const float*)d_in[14];
    const float* wf      = (const float*)d_in[15];
    float* out = (float*)d_out;

    cudaFuncSetAttribute(k_s,   cudaFuncAttributeMaxDynamicSharedMemorySize, SMEM_S);
    cudaFuncSetAttribute(k_mlp, cudaFuncAttributeMaxDynamicSharedMemorySize, SM_MLP);

    k_init <<<NCRYST, 512>>>(z, frac, lengths, angles, zproj, types, emb, ei);
    k_wconv<<<384, 256>>>(W1, Wd, W2);
    for (int l = 0; l < NLAYER; l++) {
        k_s  <<<dim3(8, NCRYST), 256, SMEM_S>>>(ei);
        k_mlp<<<NCTA_MLP, 512, SM_MLP>>>(l);
        k_agg<<<NATOM, 128>>>();
    }
    k_hw <<<NATOM, 32>>>(wf);
    k_out<<<NATOM, 128>>>(Wa, ba, ei, out);
}